// round 2
// baseline (speedup 1.0000x reference)
#include <cuda_runtime.h>
#include <math.h>

#define Bz 4
#define NN 2048
#define DD 512
#define HH 8
#define HD 64
#define MT (Bz*NN)          // 8192 rows

// ---------------- scratch (device globals; no allocation) ----------------
__device__ float g_qkv[MT * 3 * DD];      // 8192 x 1536
__device__ float g_q  [Bz*HH*NN*HD];      // (b,h,n,hd)
__device__ float g_k  [Bz*HH*NN*HD];
__device__ float g_v  [Bz*HH*NN*HD];
__device__ float g_msg[MT * DD];          // attention output (b,n,d)
__device__ float g_hin[MT * 2*DD];        // concat(x, msg@out_w+b)
__device__ float g_h1 [MT * 2*DD];        // ffn1 output / ln+gelu output

// ---------------- generic SGEMM: C[m, coff+n] = A(MxK) @ B(KxN) + bias[n] (+resid) ----
// BM=BN=128, BK=16, 256 threads, 8x8 per-thread tile.
__global__ __launch_bounds__(256) void sgemm_bias(
    const float* __restrict__ A, const float* __restrict__ B,
    const float* __restrict__ bias, const float* __restrict__ resid,
    float* __restrict__ C, int M, int N, int K, int ldc, int coff)
{
    __shared__ float As[16][128];
    __shared__ float Bs[16][128];
    const int tid = threadIdx.x;
    const int tx = tid & 15, ty = tid >> 4;
    const int m0 = blockIdx.y * 128, n0 = blockIdx.x * 128;

    float acc[8][8];
#pragma unroll
    for (int i = 0; i < 8; i++)
#pragma unroll
        for (int j = 0; j < 8; j++) acc[i][j] = 0.f;

    const float* Ab = A + (size_t)m0 * K;
    const float* Bp = B + n0;

    for (int kt = 0; kt < K; kt += 16) {
#pragma unroll
        for (int u = 0; u < 2; u++) {
            int s = tid + u * 256;          // 512 float4 slots
            int row = s >> 2, c4 = (s & 3) << 2;
            float4 a = *(const float4*)(Ab + (size_t)row * K + kt + c4);
            As[c4 + 0][row] = a.x; As[c4 + 1][row] = a.y;
            As[c4 + 2][row] = a.z; As[c4 + 3][row] = a.w;
        }
#pragma unroll
        for (int u = 0; u < 2; u++) {
            int s = tid + u * 256;
            int row = s >> 5, c4 = (s & 31) << 2;
            *(float4*)(&Bs[row][c4]) = *(const float4*)(Bp + (size_t)(kt + row) * N + c4);
        }
        __syncthreads();
#pragma unroll
        for (int kk = 0; kk < 16; kk++) {
            float ra[8], rb[8];
            *(float4*)(ra)     = *(const float4*)&As[kk][ty * 8];
            *(float4*)(ra + 4) = *(const float4*)&As[kk][ty * 8 + 4];
            *(float4*)(rb)     = *(const float4*)&Bs[kk][tx * 8];
            *(float4*)(rb + 4) = *(const float4*)&Bs[kk][tx * 8 + 4];
#pragma unroll
            for (int i = 0; i < 8; i++)
#pragma unroll
                for (int j = 0; j < 8; j++) acc[i][j] += ra[i] * rb[j];
        }
        __syncthreads();
    }
#pragma unroll
    for (int i = 0; i < 8; i++) {
        int row = m0 + ty * 8 + i;
#pragma unroll
        for (int j = 0; j < 8; j++) {
            int col = n0 + tx * 8 + j;
            float v = acc[i][j] + bias[col];
            if (resid) v += resid[(size_t)row * N + col];
            C[(size_t)row * ldc + coff + col] = v;
        }
    }
}

// ---------------- RoPE + head split ----------------
__global__ __launch_bounds__(256) void rope_split(const float* __restrict__ freqs)
{
    int idx = blockIdx.x * blockDim.x + threadIdx.x;
    if (idx >= Bz * NN * HH * 32) return;
    int i = idx & 31;
    int h = (idx >> 5) & 7;
    int n = (idx >> 8) & (NN - 1);
    int b = idx >> 19;

    float f = freqs[(size_t)(b * NN + n) * 32 + i];
    float c = cosf(f), s = sinf(f);

    size_t rowbase = (size_t)(b * NN + n) * (3 * DD);
    int qcol = h * HD + 2 * i;
    float q1 = g_qkv[rowbase + qcol],          q2 = g_qkv[rowbase + qcol + 1];
    float k1 = g_qkv[rowbase + DD + qcol],     k2 = g_qkv[rowbase + DD + qcol + 1];
    float v1 = g_qkv[rowbase + 2*DD + qcol],   v2 = g_qkv[rowbase + 2*DD + qcol + 1];

    size_t o = ((size_t)(b * HH + h) * NN + n) * HD + 2 * i;
    g_q[o]     = q1 * c - q2 * s;
    g_q[o + 1] = q1 * s + q2 * c;
    g_k[o]     = k1 * c - k2 * s;
    g_k[o + 1] = k1 * s + k2 * c;
    g_v[o]     = v1;
    g_v[o + 1] = v2;
}

// ---------------- flash attention (fp32, full attention) ----------------
// grid: (N/64 q-tiles, B*H). block: 256 threads (8x32 layout).
// Q 64x64 (stride 68), K/V 32x64 (stride 68), S 64x32 (stride 36).
// Static shared: (64*68 + 2*32*68 + 64*36)*4 = 44,032 B  (< 48 KB)
#define QP 68
#define SP 36
__global__ __launch_bounds__(256) void flash_attn()
{
    __shared__ float Qs[64 * QP];
    __shared__ float Ks[32 * QP];
    __shared__ float Vs[32 * QP];
    __shared__ float Ss[64 * SP];

    const int tid = threadIdx.x;
    const int tx = tid & 7, ty = tid >> 3;       // 8 cols-groups x 32 row-groups
    const int r0 = ty * 2, c0 = tx * 4;
    const int bh = blockIdx.y;
    const int b = bh >> 3, h = bh & 7;
    const int q0 = blockIdx.x * 64;
    const size_t base = (size_t)bh * NN * HD;

    for (int e = tid; e < 64 * 16; e += 256) {
        int r = e >> 4, c4 = (e & 15) << 2;
        *(float4*)&Qs[r * QP + c4] =
            *(const float4*)&g_q[base + (size_t)(q0 + r) * HD + c4];
    }

    float o [2][4];   // output cols c0   .. c0+3
    float oh[2][4];   // output cols c0+32.. c0+35
    float m[2], l[2];
#pragma unroll
    for (int i = 0; i < 2; i++) {
        m[i] = -INFINITY; l[i] = 0.f;
#pragma unroll
        for (int j = 0; j < 4; j++) { o[i][j] = 0.f; oh[i][j] = 0.f; }
    }

    for (int kt = 0; kt < NN / 32; kt++) {
        __syncthreads();
        for (int e = tid; e < 32 * 16; e += 256) {
            int r = e >> 4, c4 = (e & 15) << 2;
            size_t src = base + (size_t)(kt * 32 + r) * HD + c4;
            *(float4*)&Ks[r * QP + c4] = *(const float4*)&g_k[src];
            *(float4*)&Vs[r * QP + c4] = *(const float4*)&g_v[src];
        }
        __syncthreads();

        float s[2][4];
#pragma unroll
        for (int i = 0; i < 2; i++)
#pragma unroll
            for (int j = 0; j < 4; j++) s[i][j] = 0.f;

        for (int kk = 0; kk < 64; kk += 4) {
            float4 qv[2], kv[4];
#pragma unroll
            for (int i = 0; i < 2; i++) qv[i] = *(const float4*)&Qs[(r0 + i) * QP + kk];
#pragma unroll
            for (int j = 0; j < 4; j++) kv[j] = *(const float4*)&Ks[(c0 + j) * QP + kk];
#pragma unroll
            for (int i = 0; i < 2; i++)
#pragma unroll
                for (int j = 0; j < 4; j++)
                    s[i][j] += qv[i].x * kv[j].x + qv[i].y * kv[j].y
                             + qv[i].z * kv[j].z + qv[i].w * kv[j].w;
        }

#pragma unroll
        for (int i = 0; i < 2; i++) {
            float mx = -INFINITY;
#pragma unroll
            for (int j = 0; j < 4; j++) { s[i][j] *= 0.125f; mx = fmaxf(mx, s[i][j]); }
#pragma unroll
            for (int off = 4; off >= 1; off >>= 1)
                mx = fmaxf(mx, __shfl_xor_sync(0xffffffffu, mx, off));
            float nm = fmaxf(m[i], mx);
            float corr = expf(m[i] - nm);
            float rs = 0.f;
#pragma unroll
            for (int j = 0; j < 4; j++) {
                s[i][j] = expf(s[i][j] - nm);
                rs += s[i][j];
                Ss[(r0 + i) * SP + c0 + j] = s[i][j];
            }
#pragma unroll
            for (int off = 4; off >= 1; off >>= 1)
                rs += __shfl_xor_sync(0xffffffffu, rs, off);
            l[i] = l[i] * corr + rs;
            m[i] = nm;
#pragma unroll
            for (int j = 0; j < 4; j++) { o[i][j] *= corr; oh[i][j] *= corr; }
        }
        __syncthreads();

        for (int c = 0; c < 32; c++) {
            float4 vv = *(const float4*)&Vs[c * QP + c0];
            float4 vw = *(const float4*)&Vs[c * QP + c0 + 32];
            float pv0 = Ss[(r0 + 0) * SP + c];
            float pv1 = Ss[(r0 + 1) * SP + c];
            o [0][0] += pv0 * vv.x; o [0][1] += pv0 * vv.y;
            o [0][2] += pv0 * vv.z; o [0][3] += pv0 * vv.w;
            o [1][0] += pv1 * vv.x; o [1][1] += pv1 * vv.y;
            o [1][2] += pv1 * vv.z; o [1][3] += pv1 * vv.w;
            oh[0][0] += pv0 * vw.x; oh[0][1] += pv0 * vw.y;
            oh[0][2] += pv0 * vw.z; oh[0][3] += pv0 * vw.w;
            oh[1][0] += pv1 * vw.x; oh[1][1] += pv1 * vw.y;
            oh[1][2] += pv1 * vw.z; oh[1][3] += pv1 * vw.w;
        }
    }

#pragma unroll
    for (int i = 0; i < 2; i++) {
        float inv = 1.f / l[i];
        size_t row = (size_t)b * NN + (q0 + r0 + i);
#pragma unroll
        for (int j = 0; j < 4; j++) {
            g_msg[row * DD + h * HD + c0 + j]      = o [i][j] * inv;
            g_msg[row * DD + h * HD + c0 + 32 + j] = oh[i][j] * inv;
        }
    }
}

// ---------------- copy x into first half of concat buffer ----------------
__global__ __launch_bounds__(256) void copy_x(const float* __restrict__ x)
{
    int s = blockIdx.x * blockDim.x + threadIdx.x;
    if (s >= MT * 128) return;
    int row = s >> 7, c4 = s & 127;
    ((float4*)g_hin)[(size_t)row * 256 + c4] = ((const float4*)x)[s];
}

// ---------------- LayerNorm(1024) + exact GELU ----------------
__global__ __launch_bounds__(256) void ln_gelu(const float* __restrict__ gam,
                                               const float* __restrict__ bet)
{
    const int row = blockIdx.x;
    const int tid = threadIdx.x;
    float* r = g_h1 + (size_t)row * 1024;
    float4 v = *(const float4*)(r + tid * 4);
    float s  = v.x + v.y + v.z + v.w;
    float sq = v.x*v.x + v.y*v.y + v.z*v.z + v.w*v.w;
#pragma unroll
    for (int off = 16; off >= 1; off >>= 1) {
        s  += __shfl_xor_sync(0xffffffffu, s, off);
        sq += __shfl_xor_sync(0xffffffffu, sq, off);
    }
    __shared__ float rs[8], rq[8];
    if ((tid & 31) == 0) { rs[tid >> 5] = s; rq[tid >> 5] = sq; }
    __syncthreads();
    if (tid == 0) {
        float a = 0.f, bq = 0.f;
#pragma unroll
        for (int w = 0; w < 8; w++) { a += rs[w]; bq += rq[w]; }
        rs[0] = a; rq[0] = bq;
    }
    __syncthreads();
    float mu = rs[0] * (1.f / 1024.f);
    float var = rq[0] * (1.f / 1024.f) - mu * mu;
    float rstd = rsqrtf(var + 1e-5f);
    int c = tid * 4;
    float y[4] = { v.x, v.y, v.z, v.w };
    float4 ov;
    float* po = (float*)&ov;
#pragma unroll
    for (int e = 0; e < 4; e++) {
        float t = (y[e] - mu) * rstd * gam[c + e] + bet[c + e];
        po[e] = 0.5f * t * (1.f + erff(t * 0.70710678118654752440f));
    }
    *(float4*)(r + c) = ov;
}

// ---------------- host orchestration ----------------
extern "C" void kernel_launch(void* const* d_in, const int* in_sizes, int n_in,
                              void* d_out, int out_size)
{
    const float* x      = (const float*)d_in[0];
    const float* freqs  = (const float*)d_in[1];
    const float* wqkv_w = (const float*)d_in[2];
    const float* wqkv_b = (const float*)d_in[3];
    const float* out_w  = (const float*)d_in[4];
    const float* out_b  = (const float*)d_in[5];
    const float* ffn1_w = (const float*)d_in[6];
    const float* ffn1_b = (const float*)d_in[7];
    const float* ln_g   = (const float*)d_in[8];
    const float* ln_b   = (const float*)d_in[9];
    const float* ffn2_w = (const float*)d_in[10];
    const float* ffn2_b = (const float*)d_in[11];
    float* out = (float*)d_out;

    float *p_qkv, *p_msg, *p_hin, *p_h1;
    cudaGetSymbolAddress((void**)&p_qkv, g_qkv);
    cudaGetSymbolAddress((void**)&p_msg, g_msg);
    cudaGetSymbolAddress((void**)&p_hin, g_hin);
    cudaGetSymbolAddress((void**)&p_h1,  g_h1);

    // 1) qkv = x @ wqkv_w + wqkv_b    (8192 x 1536, K=512)
    sgemm_bias<<<dim3(3 * DD / 128, MT / 128), 256>>>(
        x, wqkv_w, wqkv_b, nullptr, p_qkv, MT, 3 * DD, DD, 3 * DD, 0);

    // 2) RoPE + head split
    rope_split<<<(Bz * NN * HH * 32 + 255) / 256, 256>>>(freqs);

    // copy x into concat buffer (independent)
    copy_x<<<(MT * 128 + 255) / 256, 256>>>(x);

    // 3) flash attention -> g_msg (b,n,d)
    flash_attn<<<dim3(NN / 64, Bz * HH), 256>>>();

    // 4) msg @ out_w + out_b -> second half of concat buffer
    sgemm_bias<<<dim3(DD / 128, MT / 128), 256>>>(
        p_msg, out_w, out_b, nullptr, p_hin, MT, DD, DD, 2 * DD, DD);

    // 5) hcat @ ffn1_w + ffn1_b   (8192 x 1024, K=1024)
    sgemm_bias<<<dim3(2 * DD / 128, MT / 128), 256>>>(
        p_hin, ffn1_w, ffn1_b, nullptr, p_h1, MT, 2 * DD, 2 * DD, 2 * DD, 0);

    // 6) LayerNorm + exact GELU in place
    ln_gelu<<<MT, 256>>>(ln_g, ln_b);

    // 7) out = x + act @ ffn2_w + ffn2_b  (8192 x 512, K=1024)
    sgemm_bias<<<dim3(DD / 128, MT / 128), 256>>>(
        p_h1, ffn2_w, ffn2_b, x, out, MT, DD, 2 * DD, DD, 0);
}

// round 3
// speedup vs baseline: 2.3234x; 2.3234x over previous
#include <cuda_runtime.h>
#include <math.h>

#define Bz 4
#define NN 2048
#define DD 512
#define HH 8
#define HD 64
#define MT (Bz*NN)          // 8192 rows

// ---------------- scratch (device globals; no allocation) ----------------
__device__ float g_qkv[MT * 3 * DD];      // 8192 x 1536
__device__ float g_q  [Bz*HH*NN*HD];      // (b,h,n,hd)
__device__ float g_k  [Bz*HH*NN*HD];
__device__ float g_v  [Bz*HH*NN*HD];
__device__ float g_msg[MT * DD];          // attention output (b,n,d)
__device__ float g_hin[MT * 2*DD];        // concat(x, msg@out_w+b)
__device__ float g_h1 [MT * 2*DD];        // ffn1 output / ln+gelu output

// ---------------- generic SGEMM: C[m, coff+n] = A(MxK) @ B(KxN) + bias[n] (+resid) ----
__global__ __launch_bounds__(256) void sgemm_bias(
    const float* __restrict__ A, const float* __restrict__ B,
    const float* __restrict__ bias, const float* __restrict__ resid,
    float* __restrict__ C, int M, int N, int K, int ldc, int coff)
{
    __shared__ float As[16][128];
    __shared__ float Bs[16][128];
    const int tid = threadIdx.x;
    const int tx = tid & 15, ty = tid >> 4;
    const int m0 = blockIdx.y * 128, n0 = blockIdx.x * 128;

    float acc[8][8];
#pragma unroll
    for (int i = 0; i < 8; i++)
#pragma unroll
        for (int j = 0; j < 8; j++) acc[i][j] = 0.f;

    const float* Ab = A + (size_t)m0 * K;
    const float* Bp = B + n0;

    for (int kt = 0; kt < K; kt += 16) {
#pragma unroll
        for (int u = 0; u < 2; u++) {
            int s = tid + u * 256;
            int row = s >> 2, c4 = (s & 3) << 2;
            float4 a = *(const float4*)(Ab + (size_t)row * K + kt + c4);
            As[c4 + 0][row] = a.x; As[c4 + 1][row] = a.y;
            As[c4 + 2][row] = a.z; As[c4 + 3][row] = a.w;
        }
#pragma unroll
        for (int u = 0; u < 2; u++) {
            int s = tid + u * 256;
            int row = s >> 5, c4 = (s & 31) << 2;
            *(float4*)(&Bs[row][c4]) = *(const float4*)(Bp + (size_t)(kt + row) * N + c4);
        }
        __syncthreads();
#pragma unroll
        for (int kk = 0; kk < 16; kk++) {
            float ra[8], rb[8];
            *(float4*)(ra)     = *(const float4*)&As[kk][ty * 8];
            *(float4*)(ra + 4) = *(const float4*)&As[kk][ty * 8 + 4];
            *(float4*)(rb)     = *(const float4*)&Bs[kk][tx * 8];
            *(float4*)(rb + 4) = *(const float4*)&Bs[kk][tx * 8 + 4];
#pragma unroll
            for (int i = 0; i < 8; i++)
#pragma unroll
                for (int j = 0; j < 8; j++) acc[i][j] += ra[i] * rb[j];
        }
        __syncthreads();
    }
#pragma unroll
    for (int i = 0; i < 8; i++) {
        int row = m0 + ty * 8 + i;
#pragma unroll
        for (int j = 0; j < 8; j++) {
            int col = n0 + tx * 8 + j;
            float v = acc[i][j] + bias[col];
            if (resid) v += resid[(size_t)row * N + col];
            C[(size_t)row * ldc + coff + col] = v;
        }
    }
}

// ---------------- RoPE + head split ----------------
__global__ __launch_bounds__(256) void rope_split(const float* __restrict__ freqs)
{
    int idx = blockIdx.x * blockDim.x + threadIdx.x;
    if (idx >= Bz * NN * HH * 32) return;
    int i = idx & 31;
    int h = (idx >> 5) & 7;
    int n = (idx >> 8) & (NN - 1);
    int b = idx >> 19;

    float f = freqs[(size_t)(b * NN + n) * 32 + i];
    float c = cosf(f), s = sinf(f);

    size_t rowbase = (size_t)(b * NN + n) * (3 * DD);
    int qcol = h * HD + 2 * i;
    float q1 = g_qkv[rowbase + qcol],          q2 = g_qkv[rowbase + qcol + 1];
    float k1 = g_qkv[rowbase + DD + qcol],     k2 = g_qkv[rowbase + DD + qcol + 1];
    float v1 = g_qkv[rowbase + 2*DD + qcol],   v2 = g_qkv[rowbase + 2*DD + qcol + 1];

    size_t o = ((size_t)(b * HH + h) * NN + n) * HD + 2 * i;
    g_q[o]     = q1 * c - q2 * s;
    g_q[o + 1] = q1 * s + q2 * c;
    g_k[o]     = k1 * c - k2 * s;
    g_k[o + 1] = k1 * s + k2 * c;
    g_v[o]     = v1;
    g_v[o + 1] = v2;
}

// ---------------- flash attention v2 (fp32) ----------------
// grid: (NN/128 q-tiles, B*H). block 256 threads (16 tx x 16 ty).
// Thread S-tile: 8 rows (ty*8..) x 4 cols {tx, tx+16, tx+32, tx+48}.
// Thread O-tile: 8 rows x 4 cols (tx*4 .. tx*4+3).
// K tile: stride 64, XOR-swizzled chunks (chunk' = chunk ^ (row&15)) -> conflict-free.
// Q/V/S tiles: stride 68 (broadcast-pattern reads).
// Dynamic smem: (128*68 + 64*64 + 64*68 + 128*68)*4 = 103424 B
#define QSTR 68
__global__ __launch_bounds__(256, 1) void flash_attn2()
{
    extern __shared__ float sm[];
    float* Qs = sm;                       // 128 x QSTR
    float* Ks = Qs + 128 * QSTR;          // 64 x 64 swizzled
    float* Vs = Ks + 64 * 64;             // 64 x QSTR
    float* Ss = Vs + 64 * QSTR;           // 128 x QSTR

    const int tid = threadIdx.x;
    const int tx = tid & 15, ty = tid >> 4;
    const int r0 = ty * 8;
    const int cv0 = tx * 4;
    const int bh = blockIdx.y;
    const int b = bh >> 3, h = bh & 7;
    const int q0 = blockIdx.x * 128;
    const size_t base = (size_t)bh * NN * HD;

    // load Q tile (128 x 64)
    for (int e = tid; e < 128 * 16; e += 256) {
        int r = e >> 4, cc = e & 15;
        *(float4*)&Qs[r * QSTR + cc * 4] =
            *(const float4*)&g_q[base + (size_t)(q0 + r) * HD + cc * 4];
    }

    float o[8][4];
    float m[8], l[8];
#pragma unroll
    for (int i = 0; i < 8; i++) {
        m[i] = -INFINITY; l[i] = 0.f;
#pragma unroll
        for (int j = 0; j < 4; j++) o[i][j] = 0.f;
    }

    for (int kt = 0; kt < NN / 64; kt++) {
        __syncthreads();
        // K tile: 64x64, swizzled store
        for (int e = tid; e < 64 * 16; e += 256) {
            int r = e >> 4, cc = e & 15;
            int sw = cc ^ (r & 15);
            *(float4*)&Ks[r * 64 + sw * 4] =
                *(const float4*)&g_k[base + (size_t)(kt * 64 + r) * HD + cc * 4];
        }
        // V tile: 64x64, stride QSTR
        for (int e = tid; e < 64 * 16; e += 256) {
            int r = e >> 4, cc = e & 15;
            *(float4*)&Vs[r * QSTR + cc * 4] =
                *(const float4*)&g_v[base + (size_t)(kt * 64 + r) * HD + cc * 4];
        }
        __syncthreads();

        // ---- S = Q K^T (8x4 per thread; col j -> k-row tx+16j) ----
        float s[8][4];
#pragma unroll
        for (int i = 0; i < 8; i++)
#pragma unroll
            for (int j = 0; j < 4; j++) s[i][j] = 0.f;

#pragma unroll 4
        for (int kk = 0; kk < 64; kk += 4) {
            float4 qv[8], kv[4];
            int cc = kk >> 2;
#pragma unroll
            for (int i = 0; i < 8; i++)
                qv[i] = *(const float4*)&Qs[(r0 + i) * QSTR + kk];
#pragma unroll
            for (int j = 0; j < 4; j++) {
                int row = tx + 16 * j;
                int sw = cc ^ (row & 15);
                kv[j] = *(const float4*)&Ks[row * 64 + sw * 4];
            }
#pragma unroll
            for (int i = 0; i < 8; i++)
#pragma unroll
                for (int j = 0; j < 4; j++)
                    s[i][j] += qv[i].x * kv[j].x + qv[i].y * kv[j].y
                             + qv[i].z * kv[j].z + qv[i].w * kv[j].w;
        }

        // ---- online softmax (rows owned across 16 tx lanes) ----
#pragma unroll
        for (int i = 0; i < 8; i++) {
            float mx = -INFINITY;
#pragma unroll
            for (int j = 0; j < 4; j++) { s[i][j] *= 0.125f; mx = fmaxf(mx, s[i][j]); }
#pragma unroll
            for (int off = 8; off >= 1; off >>= 1)
                mx = fmaxf(mx, __shfl_xor_sync(0xffffffffu, mx, off));
            float nm = fmaxf(m[i], mx);
            float corr = __expf(m[i] - nm);
            float rs = 0.f;
#pragma unroll
            for (int j = 0; j < 4; j++) {
                float e = __expf(s[i][j] - nm);
                rs += e;
                Ss[(r0 + i) * QSTR + tx + 16 * j] = e;
            }
#pragma unroll
            for (int off = 8; off >= 1; off >>= 1)
                rs += __shfl_xor_sync(0xffffffffu, rs, off);
            l[i] = l[i] * corr + rs;
            m[i] = nm;
#pragma unroll
            for (int j = 0; j < 4; j++) o[i][j] *= corr;
        }
        __syncthreads();

        // ---- O += S @ V (8 rows x 4 out-cols cv0..cv0+3) ----
#pragma unroll 4
        for (int kk = 0; kk < 64; kk += 4) {
            float4 sv[8], vv[4];
#pragma unroll
            for (int i = 0; i < 8; i++)
                sv[i] = *(const float4*)&Ss[(r0 + i) * QSTR + kk];
#pragma unroll
            for (int t = 0; t < 4; t++)
                vv[t] = *(const float4*)&Vs[(kk + t) * QSTR + cv0];
#pragma unroll
            for (int i = 0; i < 8; i++) {
                o[i][0] += sv[i].x * vv[0].x + sv[i].y * vv[1].x
                         + sv[i].z * vv[2].x + sv[i].w * vv[3].x;
                o[i][1] += sv[i].x * vv[0].y + sv[i].y * vv[1].y
                         + sv[i].z * vv[2].y + sv[i].w * vv[3].y;
                o[i][2] += sv[i].x * vv[0].z + sv[i].y * vv[1].z
                         + sv[i].z * vv[2].z + sv[i].w * vv[3].z;
                o[i][3] += sv[i].x * vv[0].w + sv[i].y * vv[1].w
                         + sv[i].z * vv[2].w + sv[i].w * vv[3].w;
            }
        }
    }

#pragma unroll
    for (int i = 0; i < 8; i++) {
        float inv = 1.f / l[i];
        size_t row = (size_t)b * NN + (q0 + r0 + i);
        float4 ov = make_float4(o[i][0] * inv, o[i][1] * inv,
                                o[i][2] * inv, o[i][3] * inv);
        *(float4*)&g_msg[row * DD + h * HD + cv0] = ov;
    }
}

// ---------------- copy x into first half of concat buffer ----------------
__global__ __launch_bounds__(256) void copy_x(const float* __restrict__ x)
{
    int s = blockIdx.x * blockDim.x + threadIdx.x;
    if (s >= MT * 128) return;
    int row = s >> 7, c4 = s & 127;
    ((float4*)g_hin)[(size_t)row * 256 + c4] = ((const float4*)x)[s];
}

// ---------------- LayerNorm(1024) + exact GELU ----------------
__global__ __launch_bounds__(256) void ln_gelu(const float* __restrict__ gam,
                                               const float* __restrict__ bet)
{
    const int row = blockIdx.x;
    const int tid = threadIdx.x;
    float* r = g_h1 + (size_t)row * 1024;
    float4 v = *(const float4*)(r + tid * 4);
    float s  = v.x + v.y + v.z + v.w;
    float sq = v.x*v.x + v.y*v.y + v.z*v.z + v.w*v.w;
#pragma unroll
    for (int off = 16; off >= 1; off >>= 1) {
        s  += __shfl_xor_sync(0xffffffffu, s, off);
        sq += __shfl_xor_sync(0xffffffffu, sq, off);
    }
    __shared__ float rs[8], rq[8];
    if ((tid & 31) == 0) { rs[tid >> 5] = s; rq[tid >> 5] = sq; }
    __syncthreads();
    if (tid == 0) {
        float a = 0.f, bq = 0.f;
#pragma unroll
        for (int w = 0; w < 8; w++) { a += rs[w]; bq += rq[w]; }
        rs[0] = a; rq[0] = bq;
    }
    __syncthreads();
    float mu = rs[0] * (1.f / 1024.f);
    float var = rq[0] * (1.f / 1024.f) - mu * mu;
    float rstd = rsqrtf(var + 1e-5f);
    int c = tid * 4;
    float y[4] = { v.x, v.y, v.z, v.w };
    float4 ov;
    float* po = (float*)&ov;
#pragma unroll
    for (int e = 0; e < 4; e++) {
        float t = (y[e] - mu) * rstd * gam[c + e] + bet[c + e];
        po[e] = 0.5f * t * (1.f + erff(t * 0.70710678118654752440f));
    }
    *(float4*)(r + c) = ov;
}

// ---------------- host orchestration ----------------
extern "C" void kernel_launch(void* const* d_in, const int* in_sizes, int n_in,
                              void* d_out, int out_size)
{
    const float* x      = (const float*)d_in[0];
    const float* freqs  = (const float*)d_in[1];
    const float* wqkv_w = (const float*)d_in[2];
    const float* wqkv_b = (const float*)d_in[3];
    const float* out_w  = (const float*)d_in[4];
    const float* out_b  = (const float*)d_in[5];
    const float* ffn1_w = (const float*)d_in[6];
    const float* ffn1_b = (const float*)d_in[7];
    const float* ln_g   = (const float*)d_in[8];
    const float* ln_b   = (const float*)d_in[9];
    const float* ffn2_w = (const float*)d_in[10];
    const float* ffn2_b = (const float*)d_in[11];
    float* out = (float*)d_out;

    float *p_qkv, *p_msg, *p_hin, *p_h1;
    cudaGetSymbolAddress((void**)&p_qkv, g_qkv);
    cudaGetSymbolAddress((void**)&p_msg, g_msg);
    cudaGetSymbolAddress((void**)&p_hin, g_hin);
    cudaGetSymbolAddress((void**)&p_h1,  g_h1);

    // 1) qkv = x @ wqkv_w + wqkv_b    (8192 x 1536, K=512)
    sgemm_bias<<<dim3(3 * DD / 128, MT / 128), 256>>>(
        x, wqkv_w, wqkv_b, nullptr, p_qkv, MT, 3 * DD, DD, 3 * DD, 0);

    // 2) RoPE + head split
    rope_split<<<(Bz * NN * HH * 32 + 255) / 256, 256>>>(freqs);

    // copy x into concat buffer (independent)
    copy_x<<<(MT * 128 + 255) / 256, 256>>>(x);

    // 3) flash attention -> g_msg (b,n,d)
    int fsm = (128 * QSTR + 64 * 64 + 64 * QSTR + 128 * QSTR) * sizeof(float);
    cudaFuncSetAttribute(flash_attn2, cudaFuncAttributeMaxDynamicSharedMemorySize, fsm);
    flash_attn2<<<dim3(NN / 128, Bz * HH), 256, fsm>>>();

    // 4) msg @ out_w + out_b -> second half of concat buffer
    sgemm_bias<<<dim3(DD / 128, MT / 128), 256>>>(
        p_msg, out_w, out_b, nullptr, p_hin, MT, DD, DD, 2 * DD, DD);

    // 5) hcat @ ffn1_w + ffn1_b   (8192 x 1024, K=1024)
    sgemm_bias<<<dim3(2 * DD / 128, MT / 128), 256>>>(
        p_hin, ffn1_w, ffn1_b, nullptr, p_h1, MT, 2 * DD, 2 * DD, 2 * DD, 0);

    // 6) LayerNorm + exact GELU in place
    ln_gelu<<<MT, 256>>>(ln_g, ln_b);

    // 7) out = x + act @ ffn2_w + ffn2_b  (8192 x 512, K=1024)
    sgemm_bias<<<dim3(DD / 128, MT / 128), 256>>>(
        p_h1, ffn2_w, ffn2_b, x, out, MT, DD, 2 * DD, DD, 0);
}

// round 7
// speedup vs baseline: 3.1050x; 1.3364x over previous
#include <cuda_runtime.h>
#include <cuda_bf16.h>
#include <math.h>
#include <stdint.h>

#define Bz 4
#define NN 2048
#define DD 512
#define HH 8
#define HD 64
#define MT (Bz*NN)          // 8192 rows

// ---------------- scratch (device globals; no allocation) ----------------
__device__ float g_qkv[MT * 3 * DD];
__device__ float g_q  [Bz*HH*NN*HD];
__device__ float g_k  [Bz*HH*NN*HD];
__device__ float g_v  [Bz*HH*NN*HD];
__device__ float g_msg[MT * DD];
__device__ float g_hin[MT * 2*DD];
__device__ float g_h1 [MT * 2*DD];

// bf16-split buffers
__device__ __nv_bfloat16 g_ah[MT * 1024];
__device__ __nv_bfloat16 g_al[MT * 1024];
__device__ __nv_bfloat16 g_wqkvT[2][1536 * 512];
__device__ __nv_bfloat16 g_woutT[2][512 * 512];
__device__ __nv_bfloat16 g_wff1T[2][1024 * 1024];
__device__ __nv_bfloat16 g_wff2T[2][512 * 1024];

// ================= mma.sync helpers (sm_80+ features, legal on sm_103) ====
static __device__ __forceinline__ uint32_t su32(const void* p) {
    uint32_t a;
    asm("{ .reg .u64 t; cvta.to.shared.u64 t, %1; cvt.u32.u64 %0, t; }"
        : "=r"(a) : "l"(p));
    return a;
}
static __device__ __forceinline__ void ldm_x4(uint32_t* r, uint32_t addr) {
    asm volatile("ldmatrix.sync.aligned.m8n8.x4.shared.b16 {%0,%1,%2,%3}, [%4];"
                 : "=r"(r[0]), "=r"(r[1]), "=r"(r[2]), "=r"(r[3]) : "r"(addr));
}
static __device__ __forceinline__ void ldm_x2(uint32_t* r, uint32_t addr) {
    asm volatile("ldmatrix.sync.aligned.m8n8.x2.shared.b16 {%0,%1}, [%2];"
                 : "=r"(r[0]), "=r"(r[1]) : "r"(addr));
}
static __device__ __forceinline__ void mma16816(float* c, const uint32_t* a,
                                                const uint32_t* b) {
    asm volatile(
        "mma.sync.aligned.m16n8k16.row.col.f32.bf16.bf16.f32 "
        "{%0,%1,%2,%3}, {%4,%5,%6,%7}, {%8,%9}, {%0,%1,%2,%3};"
        : "+f"(c[0]), "+f"(c[1]), "+f"(c[2]), "+f"(c[3])
        : "r"(a[0]), "r"(a[1]), "r"(a[2]), "r"(a[3]), "r"(b[0]), "r"(b[1]));
}

// ================= split / transpose pre-passes =================
__global__ __launch_bounds__(256) void asplit(
    const float* __restrict__ a, __nv_bfloat16* __restrict__ hi,
    __nv_bfloat16* __restrict__ lo, int n4)
{
    int i = blockIdx.x * blockDim.x + threadIdx.x;
    if (i >= n4) return;
    float4 v = ((const float4*)a)[i];
    __nv_bfloat16 h0 = __float2bfloat16(v.x);
    __nv_bfloat16 h1 = __float2bfloat16(v.y);
    __nv_bfloat16 h2 = __float2bfloat16(v.z);
    __nv_bfloat16 h3 = __float2bfloat16(v.w);
    __nv_bfloat162 hh0; hh0.x = h0; hh0.y = h1;
    __nv_bfloat162 hh1; hh1.x = h2; hh1.y = h3;
    __nv_bfloat162 ll0, ll1;
    ll0.x = __float2bfloat16(v.x - __bfloat162float(h0));
    ll0.y = __float2bfloat16(v.y - __bfloat162float(h1));
    ll1.x = __float2bfloat16(v.z - __bfloat162float(h2));
    ll1.y = __float2bfloat16(v.w - __bfloat162float(h3));
    *(__nv_bfloat162*)(hi + (size_t)i * 4)     = hh0;
    *(__nv_bfloat162*)(hi + (size_t)i * 4 + 2) = hh1;
    *(__nv_bfloat162*)(lo + (size_t)i * 4)     = ll0;
    *(__nv_bfloat162*)(lo + (size_t)i * 4 + 2) = ll1;
}

// w[K][N] fp32 -> wT hi/lo [N][K] bf16
__global__ void wsplit(const float* __restrict__ w,
                       __nv_bfloat16* __restrict__ th,
                       __nv_bfloat16* __restrict__ tl, int K, int N)
{
    __shared__ float t[32][33];
    int n0 = blockIdx.x * 32, k0 = blockIdx.y * 32;
    int tx = threadIdx.x, ty = threadIdx.y;   // 32 x 8
#pragma unroll
    for (int i = 0; i < 4; i++)
        t[ty + i * 8][tx] = w[(size_t)(k0 + ty + i * 8) * N + n0 + tx];
    __syncthreads();
#pragma unroll
    for (int i = 0; i < 4; i++) {
        int n = n0 + ty + i * 8, k = k0 + tx;
        float v = t[tx][ty + i * 8];
        __nv_bfloat16 h = __float2bfloat16(v);
        th[(size_t)n * K + k] = h;
        tl[(size_t)n * K + k] = __float2bfloat16(v - __bfloat162float(h));
    }
}

// ================= bf16-split GEMM via mma.sync =================
// C[m, coff+n] = sum_k A[m,k]*B[n,k] + bias (+resid). Tiles 128x128x32.
// Smem row stride 40 bf16 = 80B: 16B-aligned, and 80*r mod 128 covers all
// 8 phases over 8 rows -> conflict-free stores and ldmatrix fetches.
#define SR 40
__global__ __launch_bounds__(256, 2)
void gemm_mma(const __nv_bfloat16* __restrict__ Ah, const __nv_bfloat16* __restrict__ Al,
              const __nv_bfloat16* __restrict__ Bh, const __nv_bfloat16* __restrict__ Bl,
              const float* __restrict__ bias, const float* __restrict__ resid,
              float* __restrict__ C, int M, int N, int K, int ldc, int coff)
{
    __shared__ __nv_bfloat16 sAh[128 * SR], sAl[128 * SR];
    __shared__ __nv_bfloat16 sBh[128 * SR], sBl[128 * SR];

    const int tid = threadIdx.x;
    const int wid = tid >> 5, lane = tid & 31;
    const int wm = wid >> 2, wn = wid & 3;            // 2 x 4 warp grid
    const int m0 = blockIdx.y * 128, n0 = blockIdx.x * 128;

    const uint32_t aAh = su32(sAh), aAl = su32(sAl);
    const uint32_t aBh = su32(sBh), aBl = su32(sBl);

    float acc[4][4][4];
#pragma unroll
    for (int i = 0; i < 4; i++)
#pragma unroll
        for (int j = 0; j < 4; j++)
#pragma unroll
            for (int e = 0; e < 4; e++) acc[i][j][e] = 0.f;

    // precomputed ldmatrix per-lane byte offsets (chunk ks adds ks*32)
    uint32_t pA[4], pB[4];
    {
        int rA8 = ((lane >> 3) & 1) * 8 + (lane & 7);
        int cA  = (lane >> 4);                 // 0/1 -> k chunk +0/+1
#pragma unroll
        for (int mi = 0; mi < 4; mi++) {
            int r = wm * 64 + mi * 16 + rA8;
            pA[mi] = (uint32_t)(r * (SR * 2) + cA * 16);
        }
        int rB = (lane & 7);
        int cB = (lane >> 3) & 1;
#pragma unroll
        for (int ni = 0; ni < 4; ni++) {
            int r = wn * 32 + ni * 8 + rB;
            pB[ni] = (uint32_t)(r * (SR * 2) + cB * 16);
        }
    }

    for (int kt = 0; kt < K; kt += 32) {
        __syncthreads();
        // load 4 tiles of 128 rows x 4 16B-chunks; 512 uint4 per tile
#pragma unroll
        for (int u = 0; u < 2; u++) {
            int s = tid + u * 256;
            int r = s >> 2, c8 = s & 3;
            int so = r * SR + c8 * 8;                    // bf16 units
            size_t ga = (size_t)(m0 + r) * K + kt + c8 * 8;
            size_t gb = (size_t)(n0 + r) * K + kt + c8 * 8;
            *(uint4*)(sAh + so) = *(const uint4*)(Ah + ga);
            *(uint4*)(sAl + so) = *(const uint4*)(Al + ga);
            *(uint4*)(sBh + so) = *(const uint4*)(Bh + gb);
            *(uint4*)(sBl + so) = *(const uint4*)(Bl + gb);
        }
        __syncthreads();

#pragma unroll
        for (int ks = 0; ks < 2; ks++) {
            const uint32_t koff = ks * 32;               // 2 chunks * 16B
            uint32_t af[4][4], bh[4][2], bl[4][2];
#pragma unroll
            for (int ni = 0; ni < 4; ni++) {
                ldm_x2(bh[ni], aBh + pB[ni] + koff);
                ldm_x2(bl[ni], aBl + pB[ni] + koff);
            }
#pragma unroll
            for (int mi = 0; mi < 4; mi++)
                ldm_x4(af[mi], aAh + pA[mi] + koff);
#pragma unroll
            for (int mi = 0; mi < 4; mi++)
#pragma unroll
                for (int ni = 0; ni < 4; ni++) {
                    mma16816(acc[mi][ni], af[mi], bh[ni]);
                    mma16816(acc[mi][ni], af[mi], bl[ni]);
                }
#pragma unroll
            for (int mi = 0; mi < 4; mi++)
                ldm_x4(af[mi], aAl + pA[mi] + koff);
#pragma unroll
            for (int mi = 0; mi < 4; mi++)
#pragma unroll
                for (int ni = 0; ni < 4; ni++)
                    mma16816(acc[mi][ni], af[mi], bh[ni]);
        }
    }

    // epilogue: c-frag mapping (groupID = lane>>2, threadID = lane&3)
    const int gp = lane >> 2, tg = lane & 3;
#pragma unroll
    for (int mi = 0; mi < 4; mi++) {
#pragma unroll
        for (int ni = 0; ni < 4; ni++) {
            int col = n0 + wn * 32 + ni * 8 + tg * 2;
            float b0 = bias[col], b1 = bias[col + 1];
#pragma unroll
            for (int half = 0; half < 2; half++) {
                int row = m0 + wm * 64 + mi * 16 + gp + half * 8;
                float v0 = acc[mi][ni][half * 2 + 0] + b0;
                float v1 = acc[mi][ni][half * 2 + 1] + b1;
                if (resid) {
                    const float2 rv = *(const float2*)(resid + (size_t)row * N + col);
                    v0 += rv.x; v1 += rv.y;
                }
                *(float2*)(C + (size_t)row * ldc + coff + col) = make_float2(v0, v1);
            }
        }
    }
}

// ---------------- RoPE + head split ----------------
__global__ __launch_bounds__(256) void rope_split(const float* __restrict__ freqs)
{
    int idx = blockIdx.x * blockDim.x + threadIdx.x;
    if (idx >= Bz * NN * HH * 32) return;
    int i = idx & 31;
    int h = (idx >> 5) & 7;
    int n = (idx >> 8) & (NN - 1);
    int b = idx >> 19;

    float f = freqs[(size_t)(b * NN + n) * 32 + i];
    float c = cosf(f), s = sinf(f);

    size_t rowbase = (size_t)(b * NN + n) * (3 * DD);
    int qcol = h * HD + 2 * i;
    float q1 = g_qkv[rowbase + qcol],          q2 = g_qkv[rowbase + qcol + 1];
    float k1 = g_qkv[rowbase + DD + qcol],     k2 = g_qkv[rowbase + DD + qcol + 1];
    float v1 = g_qkv[rowbase + 2*DD + qcol],   v2 = g_qkv[rowbase + 2*DD + qcol + 1];

    size_t o = ((size_t)(b * HH + h) * NN + n) * HD + 2 * i;
    g_q[o]     = q1 * c - q2 * s;
    g_q[o + 1] = q1 * s + q2 * c;
    g_k[o]     = k1 * c - k2 * s;
    g_k[o + 1] = k1 * s + k2 * c;
    g_v[o]     = v1;
    g_v[o + 1] = v2;
}

// ---------------- flash attention v2 (fp32) ----------------
#define QSTR 68
__global__ __launch_bounds__(256, 1) void flash_attn2()
{
    extern __shared__ float sm[];
    float* Qs = sm;                       // 128 x QSTR
    float* Ks = Qs + 128 * QSTR;          // 64 x 64 swizzled
    float* Vs = Ks + 64 * 64;             // 64 x QSTR
    float* Ss = Vs + 64 * QSTR;           // 128 x QSTR

    const int tid = threadIdx.x;
    const int tx = tid & 15, ty = tid >> 4;
    const int r0 = ty * 8;
    const int cv0 = tx * 4;
    const int bh = blockIdx.y;
    const int b = bh >> 3, h = bh & 7;
    const int q0 = blockIdx.x * 128;
    const size_t base = (size_t)bh * NN * HD;

    for (int e = tid; e < 128 * 16; e += 256) {
        int r = e >> 4, cc = e & 15;
        *(float4*)&Qs[r * QSTR + cc * 4] =
            *(const float4*)&g_q[base + (size_t)(q0 + r) * HD + cc * 4];
    }

    float o[8][4];
    float m[8], l[8];
#pragma unroll
    for (int i = 0; i < 8; i++) {
        m[i] = -INFINITY; l[i] = 0.f;
#pragma unroll
        for (int j = 0; j < 4; j++) o[i][j] = 0.f;
    }

    for (int kt = 0; kt < NN / 64; kt++) {
        __syncthreads();
        for (int e = tid; e < 64 * 16; e += 256) {
            int r = e >> 4, cc = e & 15;
            int sw = cc ^ (r & 15);
            *(float4*)&Ks[r * 64 + sw * 4] =
                *(const float4*)&g_k[base + (size_t)(kt * 64 + r) * HD + cc * 4];
        }
        for (int e = tid; e < 64 * 16; e += 256) {
            int r = e >> 4, cc = e & 15;
            *(float4*)&Vs[r * QSTR + cc * 4] =
                *(const float4*)&g_v[base + (size_t)(kt * 64 + r) * HD + cc * 4];
        }
        __syncthreads();

        float s[8][4];
#pragma unroll
        for (int i = 0; i < 8; i++)
#pragma unroll
            for (int j = 0; j < 4; j++) s[i][j] = 0.f;

#pragma unroll 4
        for (int kk = 0; kk < 64; kk += 4) {
            float4 qv[8], kv[4];
            int cc = kk >> 2;
#pragma unroll
            for (int i = 0; i < 8; i++)
                qv[i] = *(const float4*)&Qs[(r0 + i) * QSTR + kk];
#pragma unroll
            for (int j = 0; j < 4; j++) {
                int row = tx + 16 * j;
                int sw = cc ^ (row & 15);
                kv[j] = *(const float4*)&Ks[row * 64 + sw * 4];
            }
#pragma unroll
            for (int i = 0; i < 8; i++)
#pragma unroll
                for (int j = 0; j < 4; j++)
                    s[i][j] += qv[i].x * kv[j].x + qv[i].y * kv[j].y
                             + qv[i].z * kv[j].z + qv[i].w * kv[j].w;
        }

#pragma unroll
        for (int i = 0; i < 8; i++) {
            float mx = -INFINITY;
#pragma unroll
            for (int j = 0; j < 4; j++) { s[i][j] *= 0.125f; mx = fmaxf(mx, s[i][j]); }
#pragma unroll
            for (int off = 8; off >= 1; off >>= 1)
                mx = fmaxf(mx, __shfl_xor_sync(0xffffffffu, mx, off));
            float nm = fmaxf(m[i], mx);
            float corr = __expf(m[i] - nm);
            float rs = 0.f;
#pragma unroll
            for (int j = 0; j < 4; j++) {
                float e = __expf(s[i][j] - nm);
                rs += e;
                Ss[(r0 + i) * QSTR + tx + 16 * j] = e;
            }
#pragma unroll
            for (int off = 8; off >= 1; off >>= 1)
                rs += __shfl_xor_sync(0xffffffffu, rs, off);
            l[i] = l[i] * corr + rs;
            m[i] = nm;
#pragma unroll
            for (int j = 0; j < 4; j++) o[i][j] *= corr;
        }
        __syncthreads();

#pragma unroll 4
        for (int kk = 0; kk < 64; kk += 4) {
            float4 sv[8], vv[4];
#pragma unroll
            for (int i = 0; i < 8; i++)
                sv[i] = *(const float4*)&Ss[(r0 + i) * QSTR + kk];
#pragma unroll
            for (int t = 0; t < 4; t++)
                vv[t] = *(const float4*)&Vs[(kk + t) * QSTR + cv0];
#pragma unroll
            for (int i = 0; i < 8; i++) {
                o[i][0] += sv[i].x * vv[0].x + sv[i].y * vv[1].x
                         + sv[i].z * vv[2].x + sv[i].w * vv[3].x;
                o[i][1] += sv[i].x * vv[0].y + sv[i].y * vv[1].y
                         + sv[i].z * vv[2].y + sv[i].w * vv[3].y;
                o[i][2] += sv[i].x * vv[0].z + sv[i].y * vv[1].z
                         + sv[i].z * vv[2].z + sv[i].w * vv[3].z;
                o[i][3] += sv[i].x * vv[0].w + sv[i].y * vv[1].w
                         + sv[i].z * vv[2].w + sv[i].w * vv[3].w;
            }
        }
    }

#pragma unroll
    for (int i = 0; i < 8; i++) {
        float inv = 1.f / l[i];
        size_t row = (size_t)b * NN + (q0 + r0 + i);
        float4 ov = make_float4(o[i][0] * inv, o[i][1] * inv,
                                o[i][2] * inv, o[i][3] * inv);
        *(float4*)&g_msg[row * DD + h * HD + cv0] = ov;
    }
}

// ---------------- copy x into first half of concat buffer ----------------
__global__ __launch_bounds__(256) void copy_x(const float* __restrict__ x)
{
    int s = blockIdx.x * blockDim.x + threadIdx.x;
    if (s >= MT * 128) return;
    int row = s >> 7, c4 = s & 127;
    ((float4*)g_hin)[(size_t)row * 256 + c4] = ((const float4*)x)[s];
}

// ---------------- LayerNorm(1024) + exact GELU ----------------
__global__ __launch_bounds__(256) void ln_gelu(const float* __restrict__ gam,
                                               const float* __restrict__ bet)
{
    const int row = blockIdx.x;
    const int tid = threadIdx.x;
    float* r = g_h1 + (size_t)row * 1024;
    float4 v = *(const float4*)(r + tid * 4);
    float s  = v.x + v.y + v.z + v.w;
    float sq = v.x*v.x + v.y*v.y + v.z*v.z + v.w*v.w;
#pragma unroll
    for (int off = 16; off >= 1; off >>= 1) {
        s  += __shfl_xor_sync(0xffffffffu, s, off);
        sq += __shfl_xor_sync(0xffffffffu, sq, off);
    }
    __shared__ float rs[8], rq[8];
    if ((tid & 31) == 0) { rs[tid >> 5] = s; rq[tid >> 5] = sq; }
    __syncthreads();
    if (tid == 0) {
        float a = 0.f, bq = 0.f;
#pragma unroll
        for (int w = 0; w < 8; w++) { a += rs[w]; bq += rq[w]; }
        rs[0] = a; rq[0] = bq;
    }
    __syncthreads();
    float mu = rs[0] * (1.f / 1024.f);
    float var = rq[0] * (1.f / 1024.f) - mu * mu;
    float rstd = rsqrtf(var + 1e-5f);
    int c = tid * 4;
    float y[4] = { v.x, v.y, v.z, v.w };
    float4 ov;
    float* po = (float*)&ov;
#pragma unroll
    for (int e = 0; e < 4; e++) {
        float t = (y[e] - mu) * rstd * gam[c + e] + bet[c + e];
        po[e] = 0.5f * t * (1.f + erff(t * 0.70710678118654752440f));
    }
    *(float4*)(r + c) = ov;
}

// ---------------- host orchestration ----------------
extern "C" void kernel_launch(void* const* d_in, const int* in_sizes, int n_in,
                              void* d_out, int out_size)
{
    const float* x      = (const float*)d_in[0];
    const float* freqs  = (const float*)d_in[1];
    const float* wqkv_w = (const float*)d_in[2];
    const float* wqkv_b = (const float*)d_in[3];
    const float* out_w  = (const float*)d_in[4];
    const float* out_b  = (const float*)d_in[5];
    const float* ffn1_w = (const float*)d_in[6];
    const float* ffn1_b = (const float*)d_in[7];
    const float* ln_g   = (const float*)d_in[8];
    const float* ln_b   = (const float*)d_in[9];
    const float* ffn2_w = (const float*)d_in[10];
    const float* ffn2_b = (const float*)d_in[11];
    float* out = (float*)d_out;

    float *p_qkv, *p_msg, *p_hin, *p_h1;
    cudaGetSymbolAddress((void**)&p_qkv, g_qkv);
    cudaGetSymbolAddress((void**)&p_msg, g_msg);
    cudaGetSymbolAddress((void**)&p_hin, g_hin);
    cudaGetSymbolAddress((void**)&p_h1,  g_h1);
    __nv_bfloat16 *ah, *al, *wq, *wo, *w1, *w2;
    cudaGetSymbolAddress((void**)&ah, g_ah);
    cudaGetSymbolAddress((void**)&al, g_al);
    cudaGetSymbolAddress((void**)&wq, g_wqkvT);
    cudaGetSymbolAddress((void**)&wo, g_woutT);
    cudaGetSymbolAddress((void**)&w1, g_wff1T);
    cudaGetSymbolAddress((void**)&w2, g_wff2T);
    __nv_bfloat16 *wqh = wq, *wql = wq + 1536 * 512;
    __nv_bfloat16 *woh = wo, *wol = wo + 512 * 512;
    __nv_bfloat16 *w1h = w1, *w1l = w1 + 1024 * 1024;
    __nv_bfloat16 *w2h = w2, *w2l = w2 + 512 * 1024;

    const int fsm = (128 * QSTR + 64 * 64 + 64 * QSTR + 128 * QSTR) * sizeof(float);
    cudaFuncSetAttribute(flash_attn2, cudaFuncAttributeMaxDynamicSharedMemorySize, fsm);

    dim3 wblk(32, 8);

    // weight transpose+split (independent)
    wsplit<<<dim3(1536 / 32, 512 / 32), wblk>>>(wqkv_w, wqh, wql, 512, 1536);
    wsplit<<<dim3(512 / 32, 512 / 32),  wblk>>>(out_w,  woh, wol, 512, 512);
    wsplit<<<dim3(1024 / 32, 1024 / 32),wblk>>>(ffn1_w, w1h, w1l, 1024, 1024);
    wsplit<<<dim3(512 / 32, 1024 / 32), wblk>>>(ffn2_w, w2h, w2l, 1024, 512);

    // 1) qkv = x @ wqkv_w + wqkv_b    (8192 x 1536, K=512)
    asplit<<<(MT * 512 / 4 + 255) / 256, 256>>>(x, ah, al, MT * 512 / 4);
    gemm_mma<<<dim3(1536 / 128, MT / 128), 256>>>(
        ah, al, wqh, wql, wqkv_b, nullptr, p_qkv, MT, 1536, 512, 1536, 0);

    // 2) RoPE + head split
    rope_split<<<(Bz * NN * HH * 32 + 255) / 256, 256>>>(freqs);

    // copy x into concat buffer (independent)
    copy_x<<<(MT * 128 + 255) / 256, 256>>>(x);

    // 3) flash attention -> g_msg
    flash_attn2<<<dim3(NN / 128, Bz * HH), 256, fsm>>>();

    // 4) msg @ out_w + out_b -> second half of concat buffer
    asplit<<<(MT * 512 / 4 + 255) / 256, 256>>>(p_msg, ah, al, MT * 512 / 4);
    gemm_mma<<<dim3(512 / 128, MT / 128), 256>>>(
        ah, al, woh, wol, out_b, nullptr, p_hin, MT, 512, 512, 1024, 512);

    // 5) hcat @ ffn1_w + ffn1_b   (8192 x 1024, K=1024)
    asplit<<<(MT * 1024 / 4 + 255) / 256, 256>>>(p_hin, ah, al, MT * 1024 / 4);
    gemm_mma<<<dim3(1024 / 128, MT / 128), 256>>>(
        ah, al, w1h, w1l, ffn1_b, nullptr, p_h1, MT, 1024, 1024, 1024, 0);

    // 6) LayerNorm + exact GELU in place
    ln_gelu<<<MT, 256>>>(ln_g, ln_b);

    // 7) out = x + act @ ffn2_w + ffn2_b  (8192 x 512, K=1024)
    asplit<<<(MT * 1024 / 4 + 255) / 256, 256>>>(p_h1, ah, al, MT * 1024 / 4);
    gemm_mma<<<dim3(512 / 128, MT / 128), 256>>>(
        ah, al, w2h, w2l, ffn2_b, x, out, MT, 512, 1024, 512, 0);
}

// round 13
// speedup vs baseline: 8.3612x; 2.6928x over previous
#include <cuda_runtime.h>
#include <cuda_bf16.h>
#include <math.h>
#include <stdint.h>

#define Bz 4
#define NN 2048
#define DD 512
#define HH 8
#define HD 64
#define MT (Bz*NN)          // 8192 rows
#define BH (Bz*HH)

// ---------------- scratch (device globals; no allocation) ----------------
__device__ float g_qkv[MT * 3 * DD];
__device__ float g_msg[MT * DD];
__device__ float g_hin[MT * 2*DD];
__device__ float g_h1 [MT * 2*DD];

// attention bf16 buffers
__device__ __nv_bfloat16 g_qh[BH * NN * HD];   // (bh, n, d), q pre-scaled by 0.125
__device__ __nv_bfloat16 g_kh[BH * NN * HD];   // (bh, n, d)
__device__ __nv_bfloat16 g_vt[BH * HD * NN];   // (bh, d, n)  transposed V

// bf16-split buffers for GEMMs
__device__ __nv_bfloat16 g_ah[MT * 1024];
__device__ __nv_bfloat16 g_al[MT * 1024];
__device__ __nv_bfloat16 g_wqkvT[2][1536 * 512];
__device__ __nv_bfloat16 g_woutT[2][512 * 512];
__device__ __nv_bfloat16 g_wff1T[2][1024 * 1024];
__device__ __nv_bfloat16 g_wff2T[2][512 * 1024];

// ================= mma.sync helpers =================
static __device__ __forceinline__ uint32_t su32(const void* p) {
    uint32_t a;
    asm("{ .reg .u64 t; cvta.to.shared.u64 t, %1; cvt.u32.u64 %0, t; }"
        : "=r"(a) : "l"(p));
    return a;
}
static __device__ __forceinline__ void ldm_x4(uint32_t* r, uint32_t addr) {
    asm volatile("ldmatrix.sync.aligned.m8n8.x4.shared.b16 {%0,%1,%2,%3}, [%4];"
                 : "=r"(r[0]), "=r"(r[1]), "=r"(r[2]), "=r"(r[3]) : "r"(addr));
}
static __device__ __forceinline__ void ldm_x2(uint32_t* r, uint32_t addr) {
    asm volatile("ldmatrix.sync.aligned.m8n8.x2.shared.b16 {%0,%1}, [%2];"
                 : "=r"(r[0]), "=r"(r[1]) : "r"(addr));
}
static __device__ __forceinline__ void mma16816(float* c, const uint32_t* a,
                                                const uint32_t* b) {
    asm volatile(
        "mma.sync.aligned.m16n8k16.row.col.f32.bf16.bf16.f32 "
        "{%0,%1,%2,%3}, {%4,%5,%6,%7}, {%8,%9}, {%0,%1,%2,%3};"
        : "+f"(c[0]), "+f"(c[1]), "+f"(c[2]), "+f"(c[3])
        : "r"(a[0]), "r"(a[1]), "r"(a[2]), "r"(a[3]), "r"(b[0]), "r"(b[1]));
}
static __device__ __forceinline__ uint32_t pack_bf16x2(float lo, float hi) {
    uint32_t d;
    asm("cvt.rn.bf16x2.f32 %0, %1, %2;" : "=r"(d) : "f"(hi), "f"(lo));
    return d;
}

// ================= split / transpose pre-passes =================
__global__ __launch_bounds__(256) void asplit(
    const float* __restrict__ a, __nv_bfloat16* __restrict__ hi,
    __nv_bfloat16* __restrict__ lo, int n4)
{
    int i = blockIdx.x * blockDim.x + threadIdx.x;
    if (i >= n4) return;
    float4 v = ((const float4*)a)[i];
    __nv_bfloat16 h0 = __float2bfloat16(v.x);
    __nv_bfloat16 h1 = __float2bfloat16(v.y);
    __nv_bfloat16 h2 = __float2bfloat16(v.z);
    __nv_bfloat16 h3 = __float2bfloat16(v.w);
    __nv_bfloat162 hh0; hh0.x = h0; hh0.y = h1;
    __nv_bfloat162 hh1; hh1.x = h2; hh1.y = h3;
    __nv_bfloat162 ll0, ll1;
    ll0.x = __float2bfloat16(v.x - __bfloat162float(h0));
    ll0.y = __float2bfloat16(v.y - __bfloat162float(h1));
    ll1.x = __float2bfloat16(v.z - __bfloat162float(h2));
    ll1.y = __float2bfloat16(v.w - __bfloat162float(h3));
    *(__nv_bfloat162*)(hi + (size_t)i * 4)     = hh0;
    *(__nv_bfloat162*)(hi + (size_t)i * 4 + 2) = hh1;
    *(__nv_bfloat162*)(lo + (size_t)i * 4)     = ll0;
    *(__nv_bfloat162*)(lo + (size_t)i * 4 + 2) = ll1;
}

__global__ void wsplit(const float* __restrict__ w,
                       __nv_bfloat16* __restrict__ th,
                       __nv_bfloat16* __restrict__ tl, int K, int N)
{
    __shared__ float t[32][33];
    int n0 = blockIdx.x * 32, k0 = blockIdx.y * 32;
    int tx = threadIdx.x, ty = threadIdx.y;   // 32 x 8
#pragma unroll
    for (int i = 0; i < 4; i++)
        t[ty + i * 8][tx] = w[(size_t)(k0 + ty + i * 8) * N + n0 + tx];
    __syncthreads();
#pragma unroll
    for (int i = 0; i < 4; i++) {
        int n = n0 + ty + i * 8, k = k0 + tx;
        float v = t[tx][ty + i * 8];
        __nv_bfloat16 h = __float2bfloat16(v);
        th[(size_t)n * K + k] = h;
        tl[(size_t)n * K + k] = __float2bfloat16(v - __bfloat162float(h));
    }
}

// ================= bf16-split GEMM via mma.sync (validated R7) =============
#define SR 40
__global__ __launch_bounds__(256, 2)
void gemm_mma(const __nv_bfloat16* __restrict__ Ah, const __nv_bfloat16* __restrict__ Al,
              const __nv_bfloat16* __restrict__ Bh, const __nv_bfloat16* __restrict__ Bl,
              const float* __restrict__ bias, const float* __restrict__ resid,
              float* __restrict__ C, int M, int N, int K, int ldc, int coff)
{
    __shared__ __nv_bfloat16 sAh[128 * SR], sAl[128 * SR];
    __shared__ __nv_bfloat16 sBh[128 * SR], sBl[128 * SR];

    const int tid = threadIdx.x;
    const int wid = tid >> 5, lane = tid & 31;
    const int wm = wid >> 2, wn = wid & 3;
    const int m0 = blockIdx.y * 128, n0 = blockIdx.x * 128;

    const uint32_t aAh = su32(sAh), aAl = su32(sAl);
    const uint32_t aBh = su32(sBh), aBl = su32(sBl);

    float acc[4][4][4];
#pragma unroll
    for (int i = 0; i < 4; i++)
#pragma unroll
        for (int j = 0; j < 4; j++)
#pragma unroll
            for (int e = 0; e < 4; e++) acc[i][j][e] = 0.f;

    uint32_t pA[4], pB[4];
    {
        int rA8 = ((lane >> 3) & 1) * 8 + (lane & 7);
        int cA  = (lane >> 4);
#pragma unroll
        for (int mi = 0; mi < 4; mi++) {
            int r = wm * 64 + mi * 16 + rA8;
            pA[mi] = (uint32_t)(r * (SR * 2) + cA * 16);
        }
        int rB = (lane & 7);
        int cB = (lane >> 3) & 1;
#pragma unroll
        for (int ni = 0; ni < 4; ni++) {
            int r = wn * 32 + ni * 8 + rB;
            pB[ni] = (uint32_t)(r * (SR * 2) + cB * 16);
        }
    }

    for (int kt = 0; kt < K; kt += 32) {
        __syncthreads();
#pragma unroll
        for (int u = 0; u < 2; u++) {
            int s = tid + u * 256;
            int r = s >> 2, c8 = s & 3;
            int so = r * SR + c8 * 8;
            size_t ga = (size_t)(m0 + r) * K + kt + c8 * 8;
            size_t gb = (size_t)(n0 + r) * K + kt + c8 * 8;
            *(uint4*)(sAh + so) = *(const uint4*)(Ah + ga);
            *(uint4*)(sAl + so) = *(const uint4*)(Al + ga);
            *(uint4*)(sBh + so) = *(const uint4*)(Bh + gb);
            *(uint4*)(sBl + so) = *(const uint4*)(Bl + gb);
        }
        __syncthreads();

#pragma unroll
        for (int ks = 0; ks < 2; ks++) {
            const uint32_t koff = ks * 32;
            uint32_t af[4][4], bh[4][2], bl[4][2];
#pragma unroll
            for (int ni = 0; ni < 4; ni++) {
                ldm_x2(bh[ni], aBh + pB[ni] + koff);
                ldm_x2(bl[ni], aBl + pB[ni] + koff);
            }
#pragma unroll
            for (int mi = 0; mi < 4; mi++)
                ldm_x4(af[mi], aAh + pA[mi] + koff);
#pragma unroll
            for (int mi = 0; mi < 4; mi++)
#pragma unroll
                for (int ni = 0; ni < 4; ni++) {
                    mma16816(acc[mi][ni], af[mi], bh[ni]);
                    mma16816(acc[mi][ni], af[mi], bl[ni]);
                }
#pragma unroll
            for (int mi = 0; mi < 4; mi++)
                ldm_x4(af[mi], aAl + pA[mi] + koff);
#pragma unroll
            for (int mi = 0; mi < 4; mi++)
#pragma unroll
                for (int ni = 0; ni < 4; ni++)
                    mma16816(acc[mi][ni], af[mi], bh[ni]);
        }
    }

    const int gp = lane >> 2, tg = lane & 3;
#pragma unroll
    for (int mi = 0; mi < 4; mi++) {
#pragma unroll
        for (int ni = 0; ni < 4; ni++) {
            int col = n0 + wn * 32 + ni * 8 + tg * 2;
            float b0 = bias[col], b1 = bias[col + 1];
#pragma unroll
            for (int half = 0; half < 2; half++) {
                int row = m0 + wm * 64 + mi * 16 + gp + half * 8;
                float v0 = acc[mi][ni][half * 2 + 0] + b0;
                float v1 = acc[mi][ni][half * 2 + 1] + b1;
                if (resid) {
                    const float2 rv = *(const float2*)(resid + (size_t)row * N + col);
                    v0 += rv.x; v1 += rv.y;
                }
                *(float2*)(C + (size_t)row * ldc + coff + col) = make_float2(v0, v1);
            }
        }
    }
}

// ---------------- RoPE -> bf16 q (x0.125), k ----------------
__global__ __launch_bounds__(256) void rope_bf(const float* __restrict__ freqs)
{
    int idx = blockIdx.x * blockDim.x + threadIdx.x;
    if (idx >= Bz * NN * HH * 32) return;
    int i = idx & 31;
    int h = (idx >> 5) & 7;
    int n = (idx >> 8) & (NN - 1);
    int b = idx >> 19;

    float f = freqs[(size_t)(b * NN + n) * 32 + i];
    float c = cosf(f), s = sinf(f);

    size_t rowbase = (size_t)(b * NN + n) * (3 * DD);
    int qcol = h * HD + 2 * i;
    float q1 = g_qkv[rowbase + qcol],      q2 = g_qkv[rowbase + qcol + 1];
    float k1 = g_qkv[rowbase + DD + qcol], k2 = g_qkv[rowbase + DD + qcol + 1];

    size_t o = ((size_t)(b * HH + h) * NN + n) * HD + 2 * i;
    __nv_bfloat162 qq, kk;
    qq.x = __float2bfloat16((q1 * c - q2 * s) * 0.125f);
    qq.y = __float2bfloat16((q1 * s + q2 * c) * 0.125f);
    kk.x = __float2bfloat16(k1 * c - k2 * s);
    kk.y = __float2bfloat16(k1 * s + k2 * c);
    *(__nv_bfloat162*)(g_qh + o) = qq;
    *(__nv_bfloat162*)(g_kh + o) = kk;
}

// ---------------- V transpose: qkv v-part -> g_vt (bh, d, n) bf16 ----------
__global__ void vtrans()
{
    __shared__ float t[32][33];
    int n0 = blockIdx.x * 32;
    int d0 = blockIdx.y * 32;
    int bh = blockIdx.z;
    int b = bh >> 3, h = bh & 7;
    int tx = threadIdx.x, ty = threadIdx.y;   // 32 x 8
#pragma unroll
    for (int i = 0; i < 4; i++) {
        int n = n0 + ty + i * 8;
        t[ty + i * 8][tx] =
            g_qkv[(size_t)(b * NN + n) * (3 * DD) + 2 * DD + h * HD + d0 + tx];
    }
    __syncthreads();
#pragma unroll
    for (int i = 0; i < 4; i++) {
        int d = d0 + ty + i * 8;
        g_vt[((size_t)bh * HD + d) * NN + n0 + tx] =
            __float2bfloat16(t[tx][ty + i * 8]);
    }
}

// ---------------- flash attention via mma.sync (bf16) ----------------
// grid (NN/128, BH), 256 thr = 8 warps; warp owns 16 q-rows.
// K tile 64x64 (n=kv rows, k=hd), Vt tile 64x64 (n=hd rows, k=kv).
// AR=72 bf16 (144B rows): >=128B data, 16B-aligned, 144r mod 128 covers all
// 8 phases over 8 rows -> conflict-free.
#define AR 72
__global__ __launch_bounds__(256, 1) void attn_mma()
{
    __shared__ __nv_bfloat16 Qs[128 * AR];
    __shared__ __nv_bfloat16 Ks[64 * AR];
    __shared__ __nv_bfloat16 Vts[64 * AR];

    const int tid = threadIdx.x;
    const int wid = tid >> 5, lane = tid & 31;
    const int gp = lane >> 2, tg = lane & 3;
    const int bh = blockIdx.y;
    const int b = bh >> 3, h = bh & 7;
    const int q0 = blockIdx.x * 128;
    const size_t qbase = (size_t)bh * NN * HD;

    const uint32_t aQ = su32(Qs), aK = su32(Ks), aV = su32(Vts);

    // load Q tile (128 x 64 bf16): 1024 uint4 -> 4 per thread
#pragma unroll
    for (int u = 0; u < 4; u++) {
        int s = tid + u * 256;
        int r = s >> 3, c8 = s & 7;
        *(uint4*)(Qs + r * AR + c8 * 8) =
            *(const uint4*)(g_qh + qbase + (size_t)(q0 + r) * HD + c8 * 8);
    }
    __syncthreads();

    // Q A-frags (4 k-chunks), rows wid*16..
    uint32_t qf[4][4];
    {
        int rA8 = ((lane >> 3) & 1) * 8 + (lane & 7);
        int cA  = (lane >> 4);
        uint32_t base = (uint32_t)((wid * 16 + rA8) * (AR * 2) + cA * 16);
#pragma unroll
        for (int kc = 0; kc < 4; kc++)
            ldm_x4(qf[kc], aQ + base + kc * 32);
    }

    // B-frag lane offset
    const uint32_t pB = (uint32_t)((lane & 7) * (AR * 2) + ((lane >> 3) & 1) * 16);

    float o[8][4];
    float m0 = -INFINITY, m1 = -INFINITY, l0 = 0.f, l1 = 0.f;
#pragma unroll
    for (int j = 0; j < 8; j++)
#pragma unroll
        for (int e = 0; e < 4; e++) o[j][e] = 0.f;

    for (int kt = 0; kt < NN / 64; kt++) {
        __syncthreads();
        // K tile: 64 rows (kv) x 64 (hd); Vt tile: 64 rows (hd) x 64 (kv)
#pragma unroll
        for (int u = 0; u < 2; u++) {
            int s = tid + u * 256;
            int r = s >> 3, c8 = s & 7;
            *(uint4*)(Ks + r * AR + c8 * 8) =
                *(const uint4*)(g_kh + qbase + (size_t)(kt * 64 + r) * HD + c8 * 8);
            *(uint4*)(Vts + r * AR + c8 * 8) =
                *(const uint4*)(g_vt + ((size_t)bh * HD + r) * NN + kt * 64 + c8 * 8);
        }
        __syncthreads();

        // ---- S = Q K^T : 8 kv n-tiles x 4 k-chunks ----
        float sc[8][4];
#pragma unroll
        for (int j = 0; j < 8; j++)
#pragma unroll
            for (int e = 0; e < 4; e++) sc[j][e] = 0.f;
#pragma unroll
        for (int j = 0; j < 8; j++) {
            uint32_t kb[4][2];
#pragma unroll
            for (int kc = 0; kc < 4; kc++)
                ldm_x2(kb[kc], aK + pB + j * 8 * (AR * 2) + kc * 32);
#pragma unroll
            for (int kc = 0; kc < 4; kc++)
                mma16816(sc[j], qf[kc], kb[kc]);
        }

        // ---- online softmax (rows gp / gp+8 of warp tile) ----
        float mx0 = -INFINITY, mx1 = -INFINITY;
#pragma unroll
        for (int j = 0; j < 8; j++) {
            mx0 = fmaxf(mx0, fmaxf(sc[j][0], sc[j][1]));
            mx1 = fmaxf(mx1, fmaxf(sc[j][2], sc[j][3]));
        }
#pragma unroll
        for (int off = 1; off <= 2; off <<= 1) {
            mx0 = fmaxf(mx0, __shfl_xor_sync(0xffffffffu, mx0, off));
            mx1 = fmaxf(mx1, __shfl_xor_sync(0xffffffffu, mx1, off));
        }
        float nm0 = fmaxf(m0, mx0), nm1 = fmaxf(m1, mx1);
        float cr0 = __expf(m0 - nm0), cr1 = __expf(m1 - nm1);
        float rs0 = 0.f, rs1 = 0.f;
        uint32_t ph[8][2];
#pragma unroll
        for (int j = 0; j < 8; j++) {
            float p0 = __expf(sc[j][0] - nm0);
            float p1 = __expf(sc[j][1] - nm0);
            float p2 = __expf(sc[j][2] - nm1);
            float p3 = __expf(sc[j][3] - nm1);
            rs0 += p0 + p1; rs1 += p2 + p3;
            ph[j][0] = pack_bf16x2(p0, p1);
            ph[j][1] = pack_bf16x2(p2, p3);
        }
#pragma unroll
        for (int off = 1; off <= 2; off <<= 1) {
            rs0 += __shfl_xor_sync(0xffffffffu, rs0, off);
            rs1 += __shfl_xor_sync(0xffffffffu, rs1, off);
        }
        l0 = l0 * cr0 + rs0;  m0 = nm0;
        l1 = l1 * cr1 + rs1;  m1 = nm1;
#pragma unroll
        for (int j = 0; j < 8; j++) {
            o[j][0] *= cr0; o[j][1] *= cr0;
            o[j][2] *= cr1; o[j][3] *= cr1;
        }

        // ---- O += P V : 4 kv k-chunks x 8 hd n-tiles ----
#pragma unroll
        for (int t = 0; t < 4; t++) {
            uint32_t af[4] = { ph[2 * t][0], ph[2 * t][1],
                               ph[2 * t + 1][0], ph[2 * t + 1][1] };
#pragma unroll
            for (int j = 0; j < 8; j++) {
                uint32_t vb[2];
                ldm_x2(vb, aV + pB + j * 8 * (AR * 2) + t * 32);
                mma16816(o[j], af, vb);
            }
        }
    }

    // write: rows q0 + wid*16 + gp (+8), cols h*64 + 8j + 2tg
    float inv0 = 1.f / l0, inv1 = 1.f / l1;
    int row0 = q0 + wid * 16 + gp;
#pragma unroll
    for (int j = 0; j < 8; j++) {
        int col = h * HD + j * 8 + tg * 2;
        *(float2*)(g_msg + (size_t)(b * NN + row0) * DD + col) =
            make_float2(o[j][0] * inv0, o[j][1] * inv0);
        *(float2*)(g_msg + (size_t)(b * NN + row0 + 8) * DD + col) =
            make_float2(o[j][2] * inv1, o[j][3] * inv1);
    }
}

// ---------------- copy x into first half of concat buffer ----------------
__global__ __launch_bounds__(256) void copy_x(const float* __restrict__ x)
{
    int s = blockIdx.x * blockDim.x + threadIdx.x;
    if (s >= MT * 128) return;
    int row = s >> 7, c4 = s & 127;
    ((float4*)g_hin)[(size_t)row * 256 + c4] = ((const float4*)x)[s];
}

// ---------------- LayerNorm(1024) + exact GELU ----------------
__global__ __launch_bounds__(256) void ln_gelu(const float* __restrict__ gam,
                                               const float* __restrict__ bet)
{
    const int row = blockIdx.x;
    const int tid = threadIdx.x;
    float* r = g_h1 + (size_t)row * 1024;
    float4 v = *(const float4*)(r + tid * 4);
    float s  = v.x + v.y + v.z + v.w;
    float sq = v.x*v.x + v.y*v.y + v.z*v.z + v.w*v.w;
#pragma unroll
    for (int off = 16; off >= 1; off >>= 1) {
        s  += __shfl_xor_sync(0xffffffffu, s, off);
        sq += __shfl_xor_sync(0xffffffffu, sq, off);
    }
    __shared__ float rs[8], rq[8];
    if ((tid & 31) == 0) { rs[tid >> 5] = s; rq[tid >> 5] = sq; }
    __syncthreads();
    if (tid == 0) {
        float a = 0.f, bq = 0.f;
#pragma unroll
        for (int w = 0; w < 8; w++) { a += rs[w]; bq += rq[w]; }
        rs[0] = a; rq[0] = bq;
    }
    __syncthreads();
    float mu = rs[0] * (1.f / 1024.f);
    float var = rq[0] * (1.f / 1024.f) - mu * mu;
    float rstd = rsqrtf(var + 1e-5f);
    int c = tid * 4;
    float y[4] = { v.x, v.y, v.z, v.w };
    float4 ov;
    float* po = (float*)&ov;
#pragma unroll
    for (int e = 0; e < 4; e++) {
        float t = (y[e] - mu) * rstd * gam[c + e] + bet[c + e];
        po[e] = 0.5f * t * (1.f + erff(t * 0.70710678118654752440f));
    }
    *(float4*)(r + c) = ov;
}

// ---------------- host orchestration ----------------
extern "C" void kernel_launch(void* const* d_in, const int* in_sizes, int n_in,
                              void* d_out, int out_size)
{
    const float* x      = (const float*)d_in[0];
    const float* freqs  = (const float*)d_in[1];
    const float* wqkv_w = (const float*)d_in[2];
    const float* wqkv_b = (const float*)d_in[3];
    const float* out_w  = (const float*)d_in[4];
    const float* out_b  = (const float*)d_in[5];
    const float* ffn1_w = (const float*)d_in[6];
    const float* ffn1_b = (const float*)d_in[7];
    const float* ln_g   = (const float*)d_in[8];
    const float* ln_b   = (const float*)d_in[9];
    const float* ffn2_w = (const float*)d_in[10];
    const float* ffn2_b = (const float*)d_in[11];
    float* out = (float*)d_out;

    float *p_qkv, *p_msg, *p_hin, *p_h1;
    cudaGetSymbolAddress((void**)&p_qkv, g_qkv);
    cudaGetSymbolAddress((void**)&p_msg, g_msg);
    cudaGetSymbolAddress((void**)&p_hin, g_hin);
    cudaGetSymbolAddress((void**)&p_h1,  g_h1);
    __nv_bfloat16 *ah, *al, *wq, *wo, *w1, *w2;
    cudaGetSymbolAddress((void**)&ah, g_ah);
    cudaGetSymbolAddress((void**)&al, g_al);
    cudaGetSymbolAddress((void**)&wq, g_wqkvT);
    cudaGetSymbolAddress((void**)&wo, g_woutT);
    cudaGetSymbolAddress((void**)&w1, g_wff1T);
    cudaGetSymbolAddress((void**)&w2, g_wff2T);
    __nv_bfloat16 *wqh = wq, *wql = wq + 1536 * 512;
    __nv_bfloat16 *woh = wo, *wol = wo + 512 * 512;
    __nv_bfloat16 *w1h = w1, *w1l = w1 + 1024 * 1024;
    __nv_bfloat16 *w2h = w2, *w2l = w2 + 512 * 1024;

    dim3 wblk(32, 8);

    // weight transpose+split (independent)
    wsplit<<<dim3(1536 / 32, 512 / 32), wblk>>>(wqkv_w, wqh, wql, 512, 1536);
    wsplit<<<dim3(512 / 32, 512 / 32),  wblk>>>(out_w,  woh, wol, 512, 512);
    wsplit<<<dim3(1024 / 32, 1024 / 32),wblk>>>(ffn1_w, w1h, w1l, 1024, 1024);
    wsplit<<<dim3(512 / 32, 1024 / 32), wblk>>>(ffn2_w, w2h, w2l, 1024, 512);

    // 1) qkv = x @ wqkv_w + wqkv_b    (8192 x 1536, K=512)
    asplit<<<(MT * 512 / 4 + 255) / 256, 256>>>(x, ah, al, MT * 512 / 4);
    gemm_mma<<<dim3(1536 / 128, MT / 128), 256>>>(
        ah, al, wqh, wql, wqkv_b, nullptr, p_qkv, MT, 1536, 512, 1536, 0);

    // 2) RoPE -> bf16 q,k ; V transpose -> bf16 vt
    rope_bf<<<(Bz * NN * HH * 32 + 255) / 256, 256>>>(freqs);
    vtrans<<<dim3(NN / 32, HD / 32, BH), wblk>>>();

    // copy x into concat buffer (independent)
    copy_x<<<(MT * 128 + 255) / 256, 256>>>(x);

    // 3) attention -> g_msg
    attn_mma<<<dim3(NN / 128, BH), 256>>>();

    // 4) msg @ out_w + out_b -> second half of concat buffer
    asplit<<<(MT * 512 / 4 + 255) / 256, 256>>>(p_msg, ah, al, MT * 512 / 4);
    gemm_mma<<<dim3(512 / 128, MT / 128), 256>>>(
        ah, al, woh, wol, out_b, nullptr, p_hin, MT, 512, 512, 1024, 512);

    // 5) hcat @ ffn1_w + ffn1_b   (8192 x 1024, K=1024)
    asplit<<<(MT * 1024 / 4 + 255) / 256, 256>>>(p_hin, ah, al, MT * 1024 / 4);
    gemm_mma<<<dim3(1024 / 128, MT / 128), 256>>>(
        ah, al, w1h, w1l, ffn1_b, nullptr, p_h1, MT, 1024, 1024, 1024, 0);

    // 6) LayerNorm + exact GELU in place
    ln_gelu<<<MT, 256>>>(ln_g, ln_b);

    // 7) out = x + act @ ffn2_w + ffn2_b  (8192 x 512, K=1024)
    asplit<<<(MT * 1024 / 4 + 255) / 256, 256>>>(p_h1, ah, al, MT * 1024 / 4);
    gemm_mma<<<dim3(512 / 128, MT / 128), 256>>>(
        ah, al, w2h, w2l, ffn2_b, x, out, MT, 512, 1024, 512, 0);
}

// round 15
// speedup vs baseline: 8.8634x; 1.0601x over previous
#include <cuda_runtime.h>
#include <cuda_bf16.h>
#include <math.h>
#include <stdint.h>

#define Bz 4
#define NN 2048
#define DD 512
#define HH 8
#define HD 64
#define MT (Bz*NN)          // 8192 rows
#define BH (Bz*HH)

// ---------------- scratch (device globals; no allocation) ----------------
__device__ float g_qkv[MT * 3 * DD];
__device__ float g_h1 [MT * 2*DD];

// attention bf16 buffers
__device__ __nv_bfloat16 g_qh[BH * NN * HD];
__device__ __nv_bfloat16 g_kh[BH * NN * HD];
__device__ __nv_bfloat16 g_vt[BH * HD * NN];

// bf16-split activation buffers
__device__ __nv_bfloat16 g_ah [MT * 1024];   // x-split / msg-split / lnact-split
__device__ __nv_bfloat16 g_al [MT * 1024];
__device__ __nv_bfloat16 g_ah2[MT * 1024];   // concat(x, outproj) split
__device__ __nv_bfloat16 g_al2[MT * 1024];
__device__ __nv_bfloat16 g_wqkvT[2][1536 * 512];
__device__ __nv_bfloat16 g_woutT[2][512 * 512];
__device__ __nv_bfloat16 g_wff1T[2][1024 * 1024];
__device__ __nv_bfloat16 g_wff2T[2][512 * 1024];

// ================= helpers =================
static __device__ __forceinline__ uint32_t su32(const void* p) {
    uint32_t a;
    asm("{ .reg .u64 t; cvta.to.shared.u64 t, %1; cvt.u32.u64 %0, t; }"
        : "=r"(a) : "l"(p));
    return a;
}
static __device__ __forceinline__ void ldm_x4(uint32_t* r, uint32_t addr) {
    asm volatile("ldmatrix.sync.aligned.m8n8.x4.shared.b16 {%0,%1,%2,%3}, [%4];"
                 : "=r"(r[0]), "=r"(r[1]), "=r"(r[2]), "=r"(r[3]) : "r"(addr));
}
static __device__ __forceinline__ void ldm_x2(uint32_t* r, uint32_t addr) {
    asm volatile("ldmatrix.sync.aligned.m8n8.x2.shared.b16 {%0,%1}, [%2];"
                 : "=r"(r[0]), "=r"(r[1]) : "r"(addr));
}
static __device__ __forceinline__ void mma16816(float* c, const uint32_t* a,
                                                const uint32_t* b) {
    asm volatile(
        "mma.sync.aligned.m16n8k16.row.col.f32.bf16.bf16.f32 "
        "{%0,%1,%2,%3}, {%4,%5,%6,%7}, {%8,%9}, {%0,%1,%2,%3};"
        : "+f"(c[0]), "+f"(c[1]), "+f"(c[2]), "+f"(c[3])
        : "r"(a[0]), "r"(a[1]), "r"(a[2]), "r"(a[3]), "r"(b[0]), "r"(b[1]));
}
static __device__ __forceinline__ uint32_t pack_bf16x2(float lo, float hi) {
    uint32_t d;
    asm("cvt.rn.bf16x2.f32 %0, %1, %2;" : "=r"(d) : "f"(hi), "f"(lo));
    return d;
}
static __device__ __forceinline__ void cp16(uint32_t dst, const void* src) {
    asm volatile("cp.async.cg.shared.global [%0], [%1], 16;"
                 :: "r"(dst), "l"(src));
}
#define CP_COMMIT() asm volatile("cp.async.commit_group;" ::: "memory")
#define CP_WAIT0()  asm volatile("cp.async.wait_group 0;" ::: "memory")
#define CP_WAIT1()  asm volatile("cp.async.wait_group 1;" ::: "memory")

static __device__ __forceinline__ void split2(float v0, float v1,
                                              __nv_bfloat162* ph, __nv_bfloat162* pl) {
    __nv_bfloat162 h, l;
    h.x = __float2bfloat16(v0); h.y = __float2bfloat16(v1);
    l.x = __float2bfloat16(v0 - __bfloat162float(h.x));
    l.y = __float2bfloat16(v1 - __bfloat162float(h.y));
    *ph = h; *pl = l;
}

// ================= split / transpose pre-passes =================
__global__ __launch_bounds__(256) void asplit(
    const float* __restrict__ a, __nv_bfloat16* __restrict__ hi,
    __nv_bfloat16* __restrict__ lo, int n4)
{
    int i = blockIdx.x * blockDim.x + threadIdx.x;
    if (i >= n4) return;
    float4 v = ((const float4*)a)[i];
    split2(v.x, v.y, (__nv_bfloat162*)(hi + (size_t)i * 4),
                     (__nv_bfloat162*)(lo + (size_t)i * 4));
    split2(v.z, v.w, (__nv_bfloat162*)(hi + (size_t)i * 4 + 2),
                     (__nv_bfloat162*)(lo + (size_t)i * 4 + 2));
}

// x [MT,512] -> split into cols 0-511 of ah2/al2 (row stride 1024)
__global__ __launch_bounds__(256) void xsplit(const float* __restrict__ x)
{
    int i = blockIdx.x * blockDim.x + threadIdx.x;   // MT*128 float4 slots
    if (i >= MT * 128) return;
    int row = i >> 7, c4 = (i & 127) * 4;
    float4 v = ((const float4*)x)[i];
    size_t o = (size_t)row * 1024 + c4;
    split2(v.x, v.y, (__nv_bfloat162*)(g_ah2 + o),     (__nv_bfloat162*)(g_al2 + o));
    split2(v.z, v.w, (__nv_bfloat162*)(g_ah2 + o + 2), (__nv_bfloat162*)(g_al2 + o + 2));
}

__global__ void wsplit(const float* __restrict__ w,
                       __nv_bfloat16* __restrict__ th,
                       __nv_bfloat16* __restrict__ tl, int K, int N)
{
    __shared__ float t[32][33];
    int n0 = blockIdx.x * 32, k0 = blockIdx.y * 32;
    int tx = threadIdx.x, ty = threadIdx.y;   // 32 x 8
#pragma unroll
    for (int i = 0; i < 4; i++)
        t[ty + i * 8][tx] = w[(size_t)(k0 + ty + i * 8) * N + n0 + tx];
    __syncthreads();
#pragma unroll
    for (int i = 0; i < 4; i++) {
        int n = n0 + ty + i * 8, k = k0 + tx;
        float v = t[tx][ty + i * 8];
        __nv_bfloat16 h = __float2bfloat16(v);
        th[(size_t)n * K + k] = h;
        tl[(size_t)n * K + k] = __float2bfloat16(v - __bfloat162float(h));
    }
}

// ================= bf16-split GEMM, cp.async double-buffered ==============
// If Oh != nullptr: write bf16 hi/lo split (bias added) instead of fp32 C.
#define SR 40
#define GSTAGE (4 * 128 * SR)            // bf16 units per stage
__global__ __launch_bounds__(256, 2)
void gemm_mma(const __nv_bfloat16* __restrict__ Ah, const __nv_bfloat16* __restrict__ Al,
              const __nv_bfloat16* __restrict__ Bh, const __nv_bfloat16* __restrict__ Bl,
              const float* __restrict__ bias, const float* __restrict__ resid,
              float* __restrict__ C,
              __nv_bfloat16* __restrict__ Oh, __nv_bfloat16* __restrict__ Ol,
              int M, int N, int K, int ldc, int coff)
{
    extern __shared__ __nv_bfloat16 dyn[];
    const int tid = threadIdx.x;
    const int wid = tid >> 5, lane = tid & 31;
    const int wm = wid >> 2, wn = wid & 3;
    const int m0 = blockIdx.y * 128, n0 = blockIdx.x * 128;
    const uint32_t sb = su32(dyn);

    float acc[4][4][4];
#pragma unroll
    for (int i = 0; i < 4; i++)
#pragma unroll
        for (int j = 0; j < 4; j++)
#pragma unroll
            for (int e = 0; e < 4; e++) acc[i][j][e] = 0.f;

    uint32_t pA[4], pB[4];
    {
        int rA8 = ((lane >> 3) & 1) * 8 + (lane & 7);
        int cA  = (lane >> 4);
#pragma unroll
        for (int mi = 0; mi < 4; mi++) {
            int r = wm * 64 + mi * 16 + rA8;
            pA[mi] = (uint32_t)(r * (SR * 2) + cA * 16);
        }
        int rB = (lane & 7);
        int cB = (lane >> 3) & 1;
#pragma unroll
        for (int ni = 0; ni < 4; ni++) {
            int r = wn * 32 + ni * 8 + rB;
            pB[ni] = (uint32_t)(r * (SR * 2) + cB * 16);
        }
    }

    // per-thread load slots (2 per sub-buffer)
    const int r0s = (tid + 0)   >> 2, c80 = ((tid + 0)   & 3) * 8;
    const int r1s = (tid + 256) >> 2, c81 = ((tid + 256) & 3) * 8;

#define GLOAD(stage, kt_) do {                                                \
    uint32_t base = sb + (uint32_t)(stage) * (GSTAGE * 2);                    \
    int ke_ = (kt_);                                                          \
    size_t ga0 = (size_t)(m0 + r0s) * K + ke_ + c80;                          \
    size_t ga1 = (size_t)(m0 + r1s) * K + ke_ + c81;                          \
    size_t gb0 = (size_t)(n0 + r0s) * K + ke_ + c80;                          \
    size_t gb1 = (size_t)(n0 + r1s) * K + ke_ + c81;                          \
    uint32_t s0 = (uint32_t)(r0s * SR + c80) * 2;                             \
    uint32_t s1 = (uint32_t)(r1s * SR + c81) * 2;                             \
    cp16(base + s0,                 Ah + ga0);                                \
    cp16(base + s1,                 Ah + ga1);                                \
    cp16(base + 128*SR*2 + s0,      Al + ga0);                                \
    cp16(base + 128*SR*2 + s1,      Al + ga1);                                \
    cp16(base + 2*128*SR*2 + s0,    Bh + gb0);                                \
    cp16(base + 2*128*SR*2 + s1,    Bh + gb1);                                \
    cp16(base + 3*128*SR*2 + s0,    Bl + gb0);                                \
    cp16(base + 3*128*SR*2 + s1,    Bl + gb1);                                \
} while (0)

    const int nkt = K >> 5;
    GLOAD(0, 0); CP_COMMIT();

    for (int kt = 0; kt < nkt; kt++) {
        if (kt + 1 < nkt) { GLOAD((kt + 1) & 1, (kt + 1) << 5); CP_COMMIT(); CP_WAIT1(); }
        else              { CP_WAIT0(); }
        __syncthreads();

        const uint32_t base = sb + (uint32_t)(kt & 1) * (GSTAGE * 2);
        const uint32_t aAh = base, aAl = base + 128*SR*2;
        const uint32_t aBh = base + 2*128*SR*2, aBl = base + 3*128*SR*2;

#pragma unroll
        for (int ks = 0; ks < 2; ks++) {
            const uint32_t koff = ks * 32;
            uint32_t af[4][4], bh[4][2], bl[4][2];
#pragma unroll
            for (int ni = 0; ni < 4; ni++) {
                ldm_x2(bh[ni], aBh + pB[ni] + koff);
                ldm_x2(bl[ni], aBl + pB[ni] + koff);
            }
#pragma unroll
            for (int mi = 0; mi < 4; mi++)
                ldm_x4(af[mi], aAh + pA[mi] + koff);
#pragma unroll
            for (int mi = 0; mi < 4; mi++)
#pragma unroll
                for (int ni = 0; ni < 4; ni++) {
                    mma16816(acc[mi][ni], af[mi], bh[ni]);
                    mma16816(acc[mi][ni], af[mi], bl[ni]);
                }
#pragma unroll
            for (int mi = 0; mi < 4; mi++)
                ldm_x4(af[mi], aAl + pA[mi] + koff);
#pragma unroll
            for (int mi = 0; mi < 4; mi++)
#pragma unroll
                for (int ni = 0; ni < 4; ni++)
                    mma16816(acc[mi][ni], af[mi], bh[ni]);
        }
        __syncthreads();
    }

    const int gp = lane >> 2, tg = lane & 3;
#pragma unroll
    for (int mi = 0; mi < 4; mi++) {
#pragma unroll
        for (int ni = 0; ni < 4; ni++) {
            int col = n0 + wn * 32 + ni * 8 + tg * 2;
            float b0 = bias[col], b1 = bias[col + 1];
#pragma unroll
            for (int half = 0; half < 2; half++) {
                int row = m0 + wm * 64 + mi * 16 + gp + half * 8;
                float v0 = acc[mi][ni][half * 2 + 0] + b0;
                float v1 = acc[mi][ni][half * 2 + 1] + b1;
                size_t o = (size_t)row * ldc + coff + col;
                if (Oh) {
                    split2(v0, v1, (__nv_bfloat162*)(Oh + o),
                                   (__nv_bfloat162*)(Ol + o));
                } else {
                    if (resid) {
                        const float2 rv = *(const float2*)(resid + (size_t)row * N + col);
                        v0 += rv.x; v1 += rv.y;
                    }
                    *(float2*)(C + o) = make_float2(v0, v1);
                }
            }
        }
    }
#undef GLOAD
}

// ---------------- RoPE -> bf16 q (x0.125), k ----------------
__global__ __launch_bounds__(256) void rope_bf(const float* __restrict__ freqs)
{
    int idx = blockIdx.x * blockDim.x + threadIdx.x;
    if (idx >= Bz * NN * HH * 32) return;
    int i = idx & 31;
    int h = (idx >> 5) & 7;
    int n = (idx >> 8) & (NN - 1);
    int b = idx >> 19;

    float f = freqs[(size_t)(b * NN + n) * 32 + i];
    float c = cosf(f), s = sinf(f);

    size_t rowbase = (size_t)(b * NN + n) * (3 * DD);
    int qcol = h * HD + 2 * i;
    float q1 = g_qkv[rowbase + qcol],      q2 = g_qkv[rowbase + qcol + 1];
    float k1 = g_qkv[rowbase + DD + qcol], k2 = g_qkv[rowbase + DD + qcol + 1];

    size_t o = ((size_t)(b * HH + h) * NN + n) * HD + 2 * i;
    __nv_bfloat162 qq, kk;
    qq.x = __float2bfloat16((q1 * c - q2 * s) * 0.125f);
    qq.y = __float2bfloat16((q1 * s + q2 * c) * 0.125f);
    kk.x = __float2bfloat16(k1 * c - k2 * s);
    kk.y = __float2bfloat16(k1 * s + k2 * c);
    *(__nv_bfloat162*)(g_qh + o) = qq;
    *(__nv_bfloat162*)(g_kh + o) = kk;
}

// ---------------- V transpose ----------------
__global__ void vtrans()
{
    __shared__ float t[32][33];
    int n0 = blockIdx.x * 32;
    int d0 = blockIdx.y * 32;
    int bh = blockIdx.z;
    int b = bh >> 3, h = bh & 7;
    int tx = threadIdx.x, ty = threadIdx.y;   // 32 x 8
#pragma unroll
    for (int i = 0; i < 4; i++) {
        int n = n0 + ty + i * 8;
        t[ty + i * 8][tx] =
            g_qkv[(size_t)(b * NN + n) * (3 * DD) + 2 * DD + h * HD + d0 + tx];
    }
    __syncthreads();
#pragma unroll
    for (int i = 0; i < 4; i++) {
        int d = d0 + ty + i * 8;
        g_vt[((size_t)bh * HD + d) * NN + n0 + tx] =
            __float2bfloat16(t[tx][ty + i * 8]);
    }
}

// ---------------- attention via mma.sync, cp.async double-buffered ---------
// Epilogue writes msg hi/lo split into g_ah/g_al (row stride 512).
#define AR 72
#define ASTG (64 * AR)     // bf16 units per K or V tile
__global__ __launch_bounds__(256, 1) void attn_mma()
{
    extern __shared__ __nv_bfloat16 adyn[];
    // layout: Q [0,128*AR) ; stage s: K at 128*AR + s*2*ASTG, V at +ASTG
    const int tid = threadIdx.x;
    const int wid = tid >> 5, lane = tid & 31;
    const int gp = lane >> 2, tg = lane & 3;
    const int bh = blockIdx.y;
    const int b = bh >> 3, h = bh & 7;
    const int q0 = blockIdx.x * 128;
    const size_t qbase = (size_t)bh * NN * HD;
    const uint32_t sb = su32(adyn);
    const uint32_t aQ = sb;

    // load Q tile (128 x 64): 1024 uint4
#pragma unroll
    for (int u = 0; u < 4; u++) {
        int s = tid + u * 256;
        int r = s >> 3, c8 = (s & 7) * 8;
        cp16(aQ + (uint32_t)(r * AR + c8) * 2,
             g_qh + qbase + (size_t)(q0 + r) * HD + c8);
    }
    CP_COMMIT();

    const int rks0 = (tid + 0)   >> 3, ck0 = ((tid + 0)   & 7) * 8;
    const int rks1 = (tid + 256) >> 3, ck1 = ((tid + 256) & 7) * 8;

#define ALOAD(stage, kt_) do {                                                 \
    uint32_t kb_ = sb + (uint32_t)(128 * AR + (stage) * 2 * ASTG) * 2;         \
    uint32_t vb_ = kb_ + ASTG * 2;                                             \
    int kv0 = (kt_) * 64;                                                      \
    cp16(kb_ + (uint32_t)(rks0 * AR + ck0) * 2,                                \
         g_kh + qbase + (size_t)(kv0 + rks0) * HD + ck0);                      \
    cp16(kb_ + (uint32_t)(rks1 * AR + ck1) * 2,                                \
         g_kh + qbase + (size_t)(kv0 + rks1) * HD + ck1);                      \
    cp16(vb_ + (uint32_t)(rks0 * AR + ck0) * 2,                                \
         g_vt + ((size_t)bh * HD + rks0) * NN + kv0 + ck0);                    \
    cp16(vb_ + (uint32_t)(rks1 * AR + ck1) * 2,                                \
         g_vt + ((size_t)bh * HD + rks1) * NN + kv0 + ck1);                    \
} while (0)

    ALOAD(0, 0); CP_COMMIT();
    CP_WAIT1();            // Q arrived (group 0 done), stage0 may be pending
    __syncthreads();

    // Q A-frags
    uint32_t qf[4][4];
    {
        int rA8 = ((lane >> 3) & 1) * 8 + (lane & 7);
        int cA  = (lane >> 4);
        uint32_t base = (uint32_t)((wid * 16 + rA8) * (AR * 2) + cA * 16);
#pragma unroll
        for (int kc = 0; kc < 4; kc++)
            ldm_x4(qf[kc], aQ + base + kc * 32);
    }
    const uint32_t pB = (uint32_t)((lane & 7) * (AR * 2) + ((lane >> 3) & 1) * 16);

    float o[8][4];
    float m0 = -INFINITY, m1 = -INFINITY, l0 = 0.f, l1 = 0.f;
#pragma unroll
    for (int j = 0; j < 8; j++)
#pragma unroll
        for (int e = 0; e < 4; e++) o[j][e] = 0.f;

    const int nkt = NN / 64;
    for (int kt = 0; kt < nkt; kt++) {
        if (kt + 1 < nkt) { ALOAD((kt + 1) & 1, kt + 1); CP_COMMIT(); CP_WAIT1(); }
        else              { CP_WAIT0(); }
        __syncthreads();

        const uint32_t aK = sb + (uint32_t)(128 * AR + (kt & 1) * 2 * ASTG) * 2;
        const uint32_t aV = aK + ASTG * 2;

        // ---- S = Q K^T ----
        float sc[8][4];
#pragma unroll
        for (int j = 0; j < 8; j++)
#pragma unroll
            for (int e = 0; e < 4; e++) sc[j][e] = 0.f;
#pragma unroll
        for (int j = 0; j < 8; j++) {
            uint32_t kb[4][2];
#pragma unroll
            for (int kc = 0; kc < 4; kc++)
                ldm_x2(kb[kc], aK + pB + j * 8 * (AR * 2) + kc * 32);
#pragma unroll
            for (int kc = 0; kc < 4; kc++)
                mma16816(sc[j], qf[kc], kb[kc]);
        }

        // ---- online softmax ----
        float mx0 = -INFINITY, mx1 = -INFINITY;
#pragma unroll
        for (int j = 0; j < 8; j++) {
            mx0 = fmaxf(mx0, fmaxf(sc[j][0], sc[j][1]));
            mx1 = fmaxf(mx1, fmaxf(sc[j][2], sc[j][3]));
        }
#pragma unroll
        for (int off = 1; off <= 2; off <<= 1) {
            mx0 = fmaxf(mx0, __shfl_xor_sync(0xffffffffu, mx0, off));
            mx1 = fmaxf(mx1, __shfl_xor_sync(0xffffffffu, mx1, off));
        }
        float nm0 = fmaxf(m0, mx0), nm1 = fmaxf(m1, mx1);
        float cr0 = __expf(m0 - nm0), cr1 = __expf(m1 - nm1);
        float rs0 = 0.f, rs1 = 0.f;
        uint32_t ph[8][2];
#pragma unroll
        for (int j = 0; j < 8; j++) {
            float p0 = __expf(sc[j][0] - nm0);
            float p1 = __expf(sc[j][1] - nm0);
            float p2 = __expf(sc[j][2] - nm1);
            float p3 = __expf(sc[j][3] - nm1);
            rs0 += p0 + p1; rs1 += p2 + p3;
            ph[j][0] = pack_bf16x2(p0, p1);
            ph[j][1] = pack_bf16x2(p2, p3);
        }
#pragma unroll
        for (int off = 1; off <= 2; off <<= 1) {
            rs0 += __shfl_xor_sync(0xffffffffu, rs0, off);
            rs1 += __shfl_xor_sync(0xffffffffu, rs1, off);
        }
        l0 = l0 * cr0 + rs0;  m0 = nm0;
        l1 = l1 * cr1 + rs1;  m1 = nm1;
#pragma unroll
        for (int j = 0; j < 8; j++) {
            o[j][0] *= cr0; o[j][1] *= cr0;
            o[j][2] *= cr1; o[j][3] *= cr1;
        }

        // ---- O += P V ----
#pragma unroll
        for (int t = 0; t < 4; t++) {
            uint32_t af[4] = { ph[2 * t][0], ph[2 * t][1],
                               ph[2 * t + 1][0], ph[2 * t + 1][1] };
#pragma unroll
            for (int j = 0; j < 8; j++) {
                uint32_t vb[2];
                ldm_x2(vb, aV + pB + j * 8 * (AR * 2) + t * 32);
                mma16816(o[j], af, vb);
            }
        }
        __syncthreads();
    }

    // epilogue: write msg split into g_ah/g_al (row stride 512)
    float inv0 = 1.f / l0, inv1 = 1.f / l1;
    int row0 = q0 + wid * 16 + gp;
#pragma unroll
    for (int j = 0; j < 8; j++) {
        int col = h * HD + j * 8 + tg * 2;
        size_t oa = (size_t)(b * NN + row0) * 512 + col;
        size_t ob = (size_t)(b * NN + row0 + 8) * 512 + col;
        split2(o[j][0] * inv0, o[j][1] * inv0,
               (__nv_bfloat162*)(g_ah + oa), (__nv_bfloat162*)(g_al + oa));
        split2(o[j][2] * inv1, o[j][3] * inv1,
               (__nv_bfloat162*)(g_ah + ob), (__nv_bfloat162*)(g_al + ob));
    }
#undef ALOAD
}

// ---------------- LayerNorm(1024) + exact GELU -> split into ah/al ---------
__global__ __launch_bounds__(256) void ln_gelu_split(const float* __restrict__ gam,
                                                     const float* __restrict__ bet)
{
    const int row = blockIdx.x;
    const int tid = threadIdx.x;
    const float* r = g_h1 + (size_t)row * 1024;
    float4 v = *(const float4*)(r + tid * 4);
    float s  = v.x + v.y + v.z + v.w;
    float sq = v.x*v.x + v.y*v.y + v.z*v.z + v.w*v.w;
#pragma unroll
    for (int off = 16; off >= 1; off >>= 1) {
        s  += __shfl_xor_sync(0xffffffffu, s, off);
        sq += __shfl_xor_sync(0xffffffffu, sq, off);
    }
    __shared__ float rs[8], rq[8];
    if ((tid & 31) == 0) { rs[tid >> 5] = s; rq[tid >> 5] = sq; }
    __syncthreads();
    if (tid == 0) {
        float a = 0.f, bq = 0.f;
#pragma unroll
        for (int w = 0; w < 8; w++) { a += rs[w]; bq += rq[w]; }
        rs[0] = a; rq[0] = bq;
    }
    __syncthreads();
    float mu = rs[0] * (1.f / 1024.f);
    float var = rq[0] * (1.f / 1024.f) - mu * mu;
    float rstd = rsqrtf(var + 1e-5f);
    int c = tid * 4;
    float y[4] = { v.x, v.y, v.z, v.w };
    float g[4];
#pragma unroll
    for (int e = 0; e < 4; e++) {
        float t = (y[e] - mu) * rstd * gam[c + e] + bet[c + e];
        g[e] = 0.5f * t * (1.f + erff(t * 0.70710678118654752440f));
    }
    size_t o = (size_t)row * 1024 + c;
    split2(g[0], g[1], (__nv_bfloat162*)(g_ah + o),     (__nv_bfloat162*)(g_al + o));
    split2(g[2], g[3], (__nv_bfloat162*)(g_ah + o + 2), (__nv_bfloat162*)(g_al + o + 2));
}

// ---------------- host orchestration ----------------
extern "C" void kernel_launch(void* const* d_in, const int* in_sizes, int n_in,
                              void* d_out, int out_size)
{
    const float* x      = (const float*)d_in[0];
    const float* freqs  = (const float*)d_in[1];
    const float* wqkv_w = (const float*)d_in[2];
    const float* wqkv_b = (const float*)d_in[3];
    const float* out_w  = (const float*)d_in[4];
    const float* out_b  = (const float*)d_in[5];
    const float* ffn1_w = (const float*)d_in[6];
    const float* ffn1_b = (const float*)d_in[7];
    const float* ln_g   = (const float*)d_in[8];
    const float* ln_b   = (const float*)d_in[9];
    const float* ffn2_w = (const float*)d_in[10];
    const float* ffn2_b = (const float*)d_in[11];
    float* out = (float*)d_out;

    float *p_qkv;
    cudaGetSymbolAddress((void**)&p_qkv, g_qkv);
    float *p_h1;
    cudaGetSymbolAddress((void**)&p_h1,  g_h1);
    __nv_bfloat16 *ah, *al, *ah2, *al2, *wq, *wo, *w1, *w2;
    cudaGetSymbolAddress((void**)&ah,  g_ah);
    cudaGetSymbolAddress((void**)&al,  g_al);
    cudaGetSymbolAddress((void**)&ah2, g_ah2);
    cudaGetSymbolAddress((void**)&al2, g_al2);
    cudaGetSymbolAddress((void**)&wq, g_wqkvT);
    cudaGetSymbolAddress((void**)&wo, g_woutT);
    cudaGetSymbolAddress((void**)&w1, g_wff1T);
    cudaGetSymbolAddress((void**)&w2, g_wff2T);
    __nv_bfloat16 *wqh = wq, *wql = wq + 1536 * 512;
    __nv_bfloat16 *woh = wo, *wol = wo + 512 * 512;
    __nv_bfloat16 *w1h = w1, *w1l = w1 + 1024 * 1024;
    __nv_bfloat16 *w2h = w2, *w2l = w2 + 512 * 1024;

    const int gsm = GSTAGE * 2 * 2 * (int)sizeof(__nv_bfloat16);   // 81920
    cudaFuncSetAttribute(gemm_mma, cudaFuncAttributeMaxDynamicSharedMemorySize, gsm);
    const int asm_ = (128 * AR + 4 * ASTG) * (int)sizeof(__nv_bfloat16); // 55296
    cudaFuncSetAttribute(attn_mma, cudaFuncAttributeMaxDynamicSharedMemorySize, asm_);

    dim3 wblk(32, 8);

    // weight transpose+split
    wsplit<<<dim3(1536 / 32, 512 / 32), wblk>>>(wqkv_w, wqh, wql, 512, 1536);
    wsplit<<<dim3(512 / 32, 512 / 32),  wblk>>>(out_w,  woh, wol, 512, 512);
    wsplit<<<dim3(1024 / 32, 1024 / 32),wblk>>>(ffn1_w, w1h, w1l, 1024, 1024);
    wsplit<<<dim3(512 / 32, 1024 / 32), wblk>>>(ffn2_w, w2h, w2l, 1024, 512);

    // 1) qkv = x @ wqkv_w + wqkv_b
    asplit<<<(MT * 512 / 4 + 255) / 256, 256>>>(x, ah, al, MT * 512 / 4);
    gemm_mma<<<dim3(1536 / 128, MT / 128), 256, gsm>>>(
        ah, al, wqh, wql, wqkv_b, nullptr, p_qkv, nullptr, nullptr,
        MT, 1536, 512, 1536, 0);

    // 2) RoPE + V transpose; x split into concat buffer
    rope_bf<<<(Bz * NN * HH * 32 + 255) / 256, 256>>>(freqs);
    vtrans<<<dim3(NN / 32, HD / 32, BH), wblk>>>();
    xsplit<<<(MT * 128 + 255) / 256, 256>>>(x);

    // 3) attention -> msg split into ah/al
    attn_mma<<<dim3(NN / 128, BH), 256, asm_>>>();

    // 4) out proj: split output into cols 512.. of ah2/al2
    gemm_mma<<<dim3(512 / 128, MT / 128), 256, gsm>>>(
        ah, al, woh, wol, out_b, nullptr, nullptr, ah2, al2,
        MT, 512, 512, 1024, 512);

    // 5) ffn1
    gemm_mma<<<dim3(1024 / 128, MT / 128), 256, gsm>>>(
        ah2, al2, w1h, w1l, ffn1_b, nullptr, p_h1, nullptr, nullptr,
        MT, 1024, 1024, 1024, 0);

    // 6) LayerNorm + GELU -> split into ah/al
    ln_gelu_split<<<MT, 256>>>(ln_g, ln_b);

    // 7) ffn2 + residual
    gemm_mma<<<dim3(512 / 128, MT / 128), 256, gsm>>>(
        ah, al, w2h, w2l, ffn2_b, x, out, nullptr, nullptr,
        MT, 512, 1024, 512, 0);
}